// round 5
// baseline (speedup 1.0000x reference)
#include <cuda_runtime.h>
#include <cstdint>

// ---------------------------------------------------------------------------
// GCN 3-layer: out = GCNConv3(relu(GCNConv2(relu(GCNConv1(x)))))
// GCNConv: out = D^-1/2 (A+I) D^-1/2 (x @ W^T) + b
// N=100000, E=1600000, C: 128 -> 128 -> 128 -> 64
//
// Root cause of R1-R4 trap 717: edge_index is int32 on device (JAX x64
// disabled downcasts jnp.int64 -> int32); reading it as int64 produced wild
// destination indices whose computed addresses fell in the shared/local
// aperture. Fix: runtime dtype probe + bounds clamp. Scalar atomics this
// round to guarantee a pass.
// ---------------------------------------------------------------------------

#define MAXN 100000
#define MAXC 128

__device__ __align__(16) float g_h[MAXN * MAXC];   // GEMM output / gather source
__device__ __align__(16) float g_a[MAXN * MAXC];   // aggregation accumulator
__device__ float g_dinv[MAXN];                     // deg -> rsqrt(deg) in place
__device__ int g_is64;                             // 1 if edge_index is int64

// ---------------------------------------------------------------------------
// dtype probe: int64 indices < 2^31 have zero high words; int32 data there
// is random node ids. 1024 samples -> P(false int64)≈0.
// ---------------------------------------------------------------------------
__global__ void probe_init_kernel() { g_is64 = 1; }

__global__ void probe_kernel(const unsigned* __restrict__ ei) {
    int i = blockIdx.x * blockDim.x + threadIdx.x;   // 0..1023
    if (i < 1024 && ei[2 * i + 1] != 0) atomicAnd(&g_is64, 0);
}

__device__ __forceinline__ void load_edge(const void* ei, int e, int g, int is64,
                                          int& s, int& d) {
    if (is64) {
        const long long* p = (const long long*)ei;
        s = (int)p[g];
        d = (int)p[e + g];
    } else {
        const int* p = (const int*)ei;
        s = p[g];
        d = p[e + g];
    }
}

// ---------------------------------------------------------------------------
// degree kernels
// ---------------------------------------------------------------------------
__global__ void deg_init_kernel(float* __restrict__ deg, int n) {
    int i = blockIdx.x * blockDim.x + threadIdx.x;
    if (i < n) deg[i] = 1.0f;  // self-loop
}

__global__ void deg_accum_kernel(const void* __restrict__ ei,
                                 float* __restrict__ deg, int e, int n) {
    int i = blockIdx.x * blockDim.x + threadIdx.x;
    if (i >= e) return;
    int is64 = g_is64;
    int s, d;
    load_edge(ei, e, i, is64, s, d);
    if ((unsigned)d < (unsigned)n) atomicAdd(&deg[d], 1.0f);
}

__global__ void deg_to_dinv_kernel(float* __restrict__ deg, int n) {
    int i = blockIdx.x * blockDim.x + threadIdx.x;
    if (i < n) deg[i] = rsqrtf(deg[i]);
}

// ---------------------------------------------------------------------------
// GEMM: H[n, COLS] = act(X[n,128]) @ W[COLS,128]^T   (optionally relu on X)
// ---------------------------------------------------------------------------
template <int COLS, bool RELU>
__global__ __launch_bounds__(256) void gemm_kernel(
    const float* __restrict__ X, const float* __restrict__ W,
    float* __restrict__ H, int n) {
    __shared__ float xs[128][33];
    __shared__ float ws[COLS][33];

    const int t = threadIdx.x;
    const int ti = t >> 4;
    const int tj = t & 15;
    constexpr int CT = COLS / 16;
    const int row0 = blockIdx.x * 128;

    float acc[8][CT];
#pragma unroll
    for (int r = 0; r < 8; r++)
#pragma unroll
        for (int c = 0; c < CT; c++) acc[r][c] = 0.0f;

    for (int kb = 0; kb < 128; kb += 32) {
        for (int idx = t; idx < 128 * 32; idx += 256) {
            int r = idx >> 5, k = idx & 31;
            int row = row0 + r;
            float v = 0.0f;
            if (row < n) {
                v = X[row * 128 + kb + k];
                if (RELU) v = fmaxf(v, 0.0f);
            }
            xs[r][k] = v;
        }
        for (int idx = t; idx < COLS * 32; idx += 256) {
            int c = idx >> 5, k = idx & 31;
            ws[c][k] = W[c * 128 + kb + k];
        }
        __syncthreads();

#pragma unroll
        for (int k = 0; k < 32; k++) {
            float xr[8], wr[CT];
#pragma unroll
            for (int r = 0; r < 8; r++) xr[r] = xs[ti + 16 * r][k];
#pragma unroll
            for (int c = 0; c < CT; c++) wr[c] = ws[tj + 16 * c][k];
#pragma unroll
            for (int r = 0; r < 8; r++)
#pragma unroll
                for (int c = 0; c < CT; c++) acc[r][c] = fmaf(xr[r], wr[c], acc[r][c]);
        }
        __syncthreads();
    }

#pragma unroll
    for (int r = 0; r < 8; r++) {
        int row = row0 + ti + 16 * r;
        if (row < n) {
#pragma unroll
            for (int c = 0; c < CT; c++)
                H[row * COLS + tj + 16 * c] = acc[r][c];
        }
    }
}

// ---------------------------------------------------------------------------
// init accumulator: A[i,:] = b + H[i,:] * dinv[i]^2   (bias + self-loop)
// ---------------------------------------------------------------------------
template <int COLS>
__global__ void init_agg_kernel(float* __restrict__ A, const float* __restrict__ H,
                                const float* __restrict__ b,
                                const float* __restrict__ dinv, int n) {
    constexpr int Q = COLS / 4;
    int idx = blockIdx.x * blockDim.x + threadIdx.x;
    if (idx >= n * Q) return;
    int i = idx / Q, q = idx - i * Q;
    float di = dinv[i];
    float w = di * di;
    float4 h = reinterpret_cast<const float4*>(H)[idx];
    float4 o;
    o.x = b[q * 4 + 0] + h.x * w;
    o.y = b[q * 4 + 1] + h.y * w;
    o.z = b[q * 4 + 2] + h.z * w;
    o.w = b[q * 4 + 3] + h.w * w;
    reinterpret_cast<float4*>(A)[idx] = o;
}

// ---------------------------------------------------------------------------
// edge scatter: A[dst,:] += H[src,:] * dinv[src]*dinv[dst]
// COLS/4 lanes per edge; vector LDG gather, scalar REDG scatter
// ---------------------------------------------------------------------------
template <int COLS>
__global__ void scatter_kernel(const void* __restrict__ ei,
                               const float* __restrict__ dinv,
                               const float* __restrict__ H,
                               float* __restrict__ A, int e, int n) {
    constexpr int L = COLS / 4;
    int tid = blockIdx.x * blockDim.x + threadIdx.x;
    int g = tid / L;
    int q = tid - g * L;
    if (g >= e) return;
    int is64 = g_is64;
    int s, d;
    load_edge(ei, e, g, is64, s, d);
    if ((unsigned)s >= (unsigned)n || (unsigned)d >= (unsigned)n) return;
    float w = dinv[s] * dinv[d];
    float4 v = reinterpret_cast<const float4*>(H + (size_t)s * COLS)[q];
    float* p = A + (size_t)d * COLS + q * 4;
    atomicAdd(p + 0, v.x * w);
    atomicAdd(p + 1, v.y * w);
    atomicAdd(p + 2, v.z * w);
    atomicAdd(p + 3, v.w * w);
}

// ---------------------------------------------------------------------------
// copy-out: plain vectorized store to d_out
// ---------------------------------------------------------------------------
__global__ void copy_out_kernel(float* __restrict__ out,
                                const float* __restrict__ A, int n4) {
    int i = blockIdx.x * blockDim.x + threadIdx.x;
    if (i < n4)
        reinterpret_cast<float4*>(out)[i] = reinterpret_cast<const float4*>(A)[i];
}

// ---------------------------------------------------------------------------
// launch
// ---------------------------------------------------------------------------
extern "C" void kernel_launch(void* const* d_in, const int* in_sizes, int n_in,
                              void* d_out, int out_size) {
    const float* x = (const float*)d_in[0];
    const void* ei = d_in[1];
    const float* W1 = (const float*)d_in[2];
    const float* b1 = (const float*)d_in[3];
    const float* W2 = (const float*)d_in[4];
    const float* b2 = (const float*)d_in[5];
    const float* W3 = (const float*)d_in[6];
    const float* b3 = (const float*)d_in[7];
    float* out = (float*)d_out;

    const int n = in_sizes[0] / 128;
    const int e = in_sizes[1] / 2;

    float *h, *a, *dinv;
    cudaGetSymbolAddress((void**)&h, g_h);
    cudaGetSymbolAddress((void**)&a, g_a);
    cudaGetSymbolAddress((void**)&dinv, g_dinv);

    const int T = 256;

    // dtype probe
    probe_init_kernel<<<1, 1>>>();
    probe_kernel<<<4, 256>>>((const unsigned*)ei);

    // degrees -> dinv
    deg_init_kernel<<<(n + T - 1) / T, T>>>(dinv, n);
    deg_accum_kernel<<<(e + T - 1) / T, T>>>(ei, dinv, e, n);
    deg_to_dinv_kernel<<<(n + T - 1) / T, T>>>(dinv, n);

    const int gemm_blocks = (n + 127) / 128;
    const int agg128 = (n * 32 + T - 1) / T;
    const int sc128 = (int)(((long long)e * 32 + T - 1) / T);

    // layer 1
    gemm_kernel<128, false><<<gemm_blocks, 256>>>(x, W1, h, n);
    init_agg_kernel<128><<<agg128, T>>>(a, h, b1, dinv, n);
    scatter_kernel<128><<<sc128, T>>>(ei, dinv, h, a, e, n);

    // layer 2
    gemm_kernel<128, true><<<gemm_blocks, 256>>>(a, W2, h, n);
    init_agg_kernel<128><<<agg128, T>>>(a, h, b2, dinv, n);
    scatter_kernel<128><<<sc128, T>>>(ei, dinv, h, a, e, n);

    // layer 3 (64 out channels): gemm reads a, writes h; a reused as accum
    gemm_kernel<64, true><<<gemm_blocks, 256>>>(a, W3, h, n);
    const int agg64 = (n * 16 + T - 1) / T;
    const int sc64 = (int)(((long long)e * 16 + T - 1) / T);
    init_agg_kernel<64><<<agg64, T>>>(a, h, b3, dinv, n);
    scatter_kernel<64><<<sc64, T>>>(ei, dinv, h, a, e, n);
    copy_out_kernel<<<(n * 16 + T - 1) / T, T>>>(out, a, n * 16);
}

// round 6
// speedup vs baseline: 2.5549x; 2.5549x over previous
#include <cuda_runtime.h>
#include <cstdint>

// ---------------------------------------------------------------------------
// GCN 3-layer, CSR-gather formulation (no atomics in hot path).
// out = GCNConv3(relu(GCNConv2(relu(GCNConv1(x)))))
// GCNConv: out = D^-1/2 (A+I) D^-1/2 (x @ W^T) + b
// N=100000, E=1600000, C: 128 -> 128 -> 128 -> 64
// ---------------------------------------------------------------------------

#define MAXN 100000
#define MAXE 1600000
#define SCAN_B 1024

__device__ __align__(16) float g_h[MAXN * 128];   // GEMM output / gather source
__device__ __align__(16) float g_a[MAXN * 128];   // aggregation result
__device__ float g_dinv[MAXN];
__device__ int g_cnt[MAXN];                       // in-degree (excl self-loop)
__device__ int g_fill[MAXN];                      // placement cursors
__device__ int g_rowptr[MAXN];
__device__ int g_incl[MAXN];
__device__ int g_bsum[256];
__device__ int g_csr[MAXE];                       // src ids grouped by dst
__device__ int g_is64;

// ---------------------------------------------------------------------------
// edge dtype probe (int64 vs int32 materialization)
// ---------------------------------------------------------------------------
__global__ void probe_init_kernel() { g_is64 = 1; }
__global__ void probe_kernel(const unsigned* __restrict__ ei) {
    int i = blockIdx.x * blockDim.x + threadIdx.x;
    if (i < 1024 && ei[2 * i + 1] != 0) atomicAnd(&g_is64, 0);
}

__device__ __forceinline__ void load_edge(const void* ei, int e, int g, int is64,
                                          int& s, int& d) {
    if (is64) {
        const long long* p = (const long long*)ei;
        s = (int)p[g];
        d = (int)p[e + g];
    } else {
        const int* p = (const int*)ei;
        s = p[g];
        d = p[e + g];
    }
}

// ---------------------------------------------------------------------------
// CSR build
// ---------------------------------------------------------------------------
__global__ void zero2_kernel(int* __restrict__ a, int* __restrict__ b, int n) {
    int i = blockIdx.x * blockDim.x + threadIdx.x;
    if (i < n) { a[i] = 0; b[i] = 0; }
}

__global__ void count_kernel(const void* __restrict__ ei, int* __restrict__ cnt,
                             int e, int n) {
    int i = blockIdx.x * blockDim.x + threadIdx.x;
    if (i >= e) return;
    int s, d;
    load_edge(ei, e, i, g_is64, s, d);
    if ((unsigned)d < (unsigned)n) atomicAdd(&cnt[d], 1);
}

__global__ void dinv_kernel(const int* __restrict__ cnt, float* __restrict__ dinv,
                            int n) {
    int i = blockIdx.x * blockDim.x + threadIdx.x;
    if (i < n) dinv[i] = rsqrtf((float)cnt[i] + 1.0f);   // +1 self-loop
}

__global__ __launch_bounds__(SCAN_B) void scan_block_kernel(
    const int* __restrict__ cnt, int* __restrict__ incl, int* __restrict__ bsum,
    int n) {
    __shared__ int sm[SCAN_B];
    int i = blockIdx.x * SCAN_B + threadIdx.x;
    int v = (i < n) ? cnt[i] : 0;
    sm[threadIdx.x] = v;
    __syncthreads();
#pragma unroll
    for (int off = 1; off < SCAN_B; off <<= 1) {
        int t = (threadIdx.x >= off) ? sm[threadIdx.x - off] : 0;
        __syncthreads();
        sm[threadIdx.x] += t;
        __syncthreads();
    }
    if (i < n) incl[i] = sm[threadIdx.x];
    if (threadIdx.x == SCAN_B - 1) bsum[blockIdx.x] = sm[SCAN_B - 1];
}

__global__ __launch_bounds__(256) void scan_bsum_kernel(int* __restrict__ bsum,
                                                        int nb) {
    __shared__ int sm[256];
    int v = (threadIdx.x < nb) ? bsum[threadIdx.x] : 0;
    sm[threadIdx.x] = v;
    __syncthreads();
#pragma unroll
    for (int off = 1; off < 256; off <<= 1) {
        int t = (threadIdx.x >= off) ? sm[threadIdx.x - off] : 0;
        __syncthreads();
        sm[threadIdx.x] += t;
        __syncthreads();
    }
    if (threadIdx.x < nb) bsum[threadIdx.x] = sm[threadIdx.x] - v;  // exclusive
}

__global__ void scan_final_kernel(const int* __restrict__ incl,
                                  const int* __restrict__ cnt,
                                  const int* __restrict__ bsum,
                                  int* __restrict__ rowptr, int n) {
    int i = blockIdx.x * blockDim.x + threadIdx.x;
    if (i < n) rowptr[i] = incl[i] - cnt[i] + bsum[i / SCAN_B];
}

__global__ void fill_csr_kernel(const void* __restrict__ ei,
                                const int* __restrict__ rowptr,
                                int* __restrict__ fill, int* __restrict__ csr,
                                int e, int n) {
    int i = blockIdx.x * blockDim.x + threadIdx.x;
    if (i >= e) return;
    int s, d;
    load_edge(ei, e, i, g_is64, s, d);
    if ((unsigned)s >= (unsigned)n || (unsigned)d >= (unsigned)n) return;
    int pos = rowptr[d] + atomicAdd(&fill[d], 1);
    csr[pos] = s;
}

// ---------------------------------------------------------------------------
// GEMM: H[n, COLS] = act(X[n,128]) @ W[COLS,128]^T
// ---------------------------------------------------------------------------
template <int COLS, bool RELU>
__global__ __launch_bounds__(256) void gemm_kernel(
    const float* __restrict__ X, const float* __restrict__ W,
    float* __restrict__ H, int n) {
    __shared__ float xs[128][33];
    __shared__ float ws[COLS][33];

    const int t = threadIdx.x;
    const int ti = t >> 4;
    const int tj = t & 15;
    constexpr int CT = COLS / 16;
    const int row0 = blockIdx.x * 128;

    float acc[8][CT];
#pragma unroll
    for (int r = 0; r < 8; r++)
#pragma unroll
        for (int c = 0; c < CT; c++) acc[r][c] = 0.0f;

    for (int kb = 0; kb < 128; kb += 32) {
        for (int idx = t; idx < 128 * 32; idx += 256) {
            int r = idx >> 5, k = idx & 31;
            int row = row0 + r;
            float v = 0.0f;
            if (row < n) {
                v = X[row * 128 + kb + k];
                if (RELU) v = fmaxf(v, 0.0f);
            }
            xs[r][k] = v;
        }
        for (int idx = t; idx < COLS * 32; idx += 256) {
            int c = idx >> 5, k = idx & 31;
            ws[c][k] = W[c * 128 + kb + k];
        }
        __syncthreads();

#pragma unroll
        for (int k = 0; k < 32; k++) {
            float xr[8], wr[CT];
#pragma unroll
            for (int r = 0; r < 8; r++) xr[r] = xs[ti + 16 * r][k];
#pragma unroll
            for (int c = 0; c < CT; c++) wr[c] = ws[tj + 16 * c][k];
#pragma unroll
            for (int r = 0; r < 8; r++)
#pragma unroll
                for (int c = 0; c < CT; c++) acc[r][c] = fmaf(xr[r], wr[c], acc[r][c]);
        }
        __syncthreads();
    }

#pragma unroll
    for (int r = 0; r < 8; r++) {
        int row = row0 + ti + 16 * r;
        if (row < n) {
#pragma unroll
            for (int c = 0; c < CT; c++)
                H[row * COLS + tj + 16 * c] = acc[r][c];
        }
    }
}

// ---------------------------------------------------------------------------
// gather (one warp per node): A[d] = b + dinv[d]^2*H[d] + sum_e dinv[s]dinv[d]H[s]
// COLS=128: 4 ch/lane (float4). COLS=64: 2 ch/lane (float2).
// ---------------------------------------------------------------------------
__global__ __launch_bounds__(256) void gather128_kernel(
    const int* __restrict__ csr, const int* __restrict__ rowptr,
    const int* __restrict__ cnt, const float* __restrict__ dinv,
    const float* __restrict__ H, const float* __restrict__ b,
    float* __restrict__ A, int n) {
    int warp = (blockIdx.x * blockDim.x + threadIdx.x) >> 5;
    int lane = threadIdx.x & 31;
    if (warp >= n) return;
    const int d = warp;
    const int start = rowptr[d];
    const int c = cnt[d];
    const float dd = dinv[d];

    float4 acc;
    {
        float w0 = dd * dd;
        float4 hv = reinterpret_cast<const float4*>(H + (size_t)d * 128)[lane];
        const float4 bv = reinterpret_cast<const float4*>(b)[lane];
        acc.x = bv.x + hv.x * w0;
        acc.y = bv.y + hv.y * w0;
        acc.z = bv.z + hv.z * w0;
        acc.w = bv.w + hv.w * w0;
    }

    for (int j0 = 0; j0 < c; j0 += 32) {
        int valid = j0 + lane < c;
        int s = valid ? csr[start + j0 + lane] : 0;
        float ws = valid ? dinv[s] * dd : 0.0f;
        int m = min(32, c - j0);
#pragma unroll 4
        for (int k = 0; k < m; k++) {
            int sk = __shfl_sync(0xffffffffu, s, k);
            float wk = __shfl_sync(0xffffffffu, ws, k);
            float4 v = reinterpret_cast<const float4*>(H + (size_t)sk * 128)[lane];
            acc.x = fmaf(v.x, wk, acc.x);
            acc.y = fmaf(v.y, wk, acc.y);
            acc.z = fmaf(v.z, wk, acc.z);
            acc.w = fmaf(v.w, wk, acc.w);
        }
    }
    reinterpret_cast<float4*>(A + (size_t)d * 128)[lane] = acc;
}

__global__ __launch_bounds__(256) void gather64_kernel(
    const int* __restrict__ csr, const int* __restrict__ rowptr,
    const int* __restrict__ cnt, const float* __restrict__ dinv,
    const float* __restrict__ H, const float* __restrict__ b,
    float* __restrict__ A, int n) {
    int warp = (blockIdx.x * blockDim.x + threadIdx.x) >> 5;
    int lane = threadIdx.x & 31;
    if (warp >= n) return;
    const int d = warp;
    const int start = rowptr[d];
    const int c = cnt[d];
    const float dd = dinv[d];

    float2 acc;
    {
        float w0 = dd * dd;
        float2 hv = reinterpret_cast<const float2*>(H + (size_t)d * 64)[lane];
        float2 bv = reinterpret_cast<const float2*>(b)[lane];
        acc.x = bv.x + hv.x * w0;
        acc.y = bv.y + hv.y * w0;
    }

    for (int j0 = 0; j0 < c; j0 += 32) {
        int valid = j0 + lane < c;
        int s = valid ? csr[start + j0 + lane] : 0;
        float ws = valid ? dinv[s] * dd : 0.0f;
        int m = min(32, c - j0);
#pragma unroll 4
        for (int k = 0; k < m; k++) {
            int sk = __shfl_sync(0xffffffffu, s, k);
            float wk = __shfl_sync(0xffffffffu, ws, k);
            float2 v = reinterpret_cast<const float2*>(H + (size_t)sk * 64)[lane];
            acc.x = fmaf(v.x, wk, acc.x);
            acc.y = fmaf(v.y, wk, acc.y);
        }
    }
    reinterpret_cast<float2*>(A + (size_t)d * 64)[lane] = acc;
}

// ---------------------------------------------------------------------------
// copy-out
// ---------------------------------------------------------------------------
__global__ void copy_out_kernel(float* __restrict__ out,
                                const float* __restrict__ A, int n4) {
    int i = blockIdx.x * blockDim.x + threadIdx.x;
    if (i < n4)
        reinterpret_cast<float4*>(out)[i] = reinterpret_cast<const float4*>(A)[i];
}

// ---------------------------------------------------------------------------
// launch
// ---------------------------------------------------------------------------
extern "C" void kernel_launch(void* const* d_in, const int* in_sizes, int n_in,
                              void* d_out, int out_size) {
    const float* x = (const float*)d_in[0];
    const void* ei = d_in[1];
    const float* W1 = (const float*)d_in[2];
    const float* b1 = (const float*)d_in[3];
    const float* W2 = (const float*)d_in[4];
    const float* b2 = (const float*)d_in[5];
    const float* W3 = (const float*)d_in[6];
    const float* b3 = (const float*)d_in[7];
    float* out = (float*)d_out;

    const int n = in_sizes[0] / 128;
    const int e = in_sizes[1] / 2;

    float *h, *a, *dinv;
    int *cnt, *fill, *rowptr, *incl, *bsum, *csr;
    cudaGetSymbolAddress((void**)&h, g_h);
    cudaGetSymbolAddress((void**)&a, g_a);
    cudaGetSymbolAddress((void**)&dinv, g_dinv);
    cudaGetSymbolAddress((void**)&cnt, g_cnt);
    cudaGetSymbolAddress((void**)&fill, g_fill);
    cudaGetSymbolAddress((void**)&rowptr, g_rowptr);
    cudaGetSymbolAddress((void**)&incl, g_incl);
    cudaGetSymbolAddress((void**)&bsum, g_bsum);
    cudaGetSymbolAddress((void**)&csr, g_csr);

    const int T = 256;
    const int nb = (n + SCAN_B - 1) / SCAN_B;

    probe_init_kernel<<<1, 1>>>();
    probe_kernel<<<4, 256>>>((const unsigned*)ei);

    // CSR build
    zero2_kernel<<<(n + T - 1) / T, T>>>(cnt, fill, n);
    count_kernel<<<(e + T - 1) / T, T>>>(ei, cnt, e, n);
    dinv_kernel<<<(n + T - 1) / T, T>>>(cnt, dinv, n);
    scan_block_kernel<<<nb, SCAN_B>>>(cnt, incl, bsum, n);
    scan_bsum_kernel<<<1, 256>>>(bsum, nb);
    scan_final_kernel<<<(n + T - 1) / T, T>>>(incl, cnt, bsum, rowptr, n);
    fill_csr_kernel<<<(e + T - 1) / T, T>>>(ei, rowptr, fill, csr, e, n);

    const int gemm_blocks = (n + 127) / 128;
    const int gather_blocks = (n * 32 + T - 1) / T;   // warp per node

    // layer 1
    gemm_kernel<128, false><<<gemm_blocks, 256>>>(x, W1, h, n);
    gather128_kernel<<<gather_blocks, T>>>(csr, rowptr, cnt, dinv, h, b1, a, n);

    // layer 2
    gemm_kernel<128, true><<<gemm_blocks, 256>>>(a, W2, h, n);
    gather128_kernel<<<gather_blocks, T>>>(csr, rowptr, cnt, dinv, h, b2, a, n);

    // layer 3 (64 ch): gemm reads a, writes h; gather h -> a; copy a -> out
    gemm_kernel<64, true><<<gemm_blocks, 256>>>(a, W3, h, n);
    gather64_kernel<<<gather_blocks, T>>>(csr, rowptr, cnt, dinv, h, b3, a, n);
    copy_out_kernel<<<(n * 16 + T - 1) / T, T>>>(out, a, n * 16);
}

// round 7
// speedup vs baseline: 2.7979x; 1.0951x over previous
#include <cuda_runtime.h>
#include <cstdint>

// ---------------------------------------------------------------------------
// GCN 3-layer, CSR-gather + f32x2-packed GEMM.
// out = GCNConv3(relu(GCNConv2(relu(GCNConv1(x)))))
// GCNConv: out = D^-1/2 (A+I) D^-1/2 (x @ W^T) + b
// N=100000, E=1600000, C: 128 -> 128 -> 128 -> 64
// ---------------------------------------------------------------------------

#define MAXN 100000
#define MAXE 1600000
#define SCAN_B 1024

__device__ __align__(16) float g_h[MAXN * 128];
__device__ __align__(16) float g_a[MAXN * 128];
__device__ float g_dinv[MAXN];
__device__ int g_cnt[MAXN];
__device__ int g_fill[MAXN];
__device__ int g_rowptr[MAXN];
__device__ int g_incl[MAXN];
__device__ int g_bsum[256];
__device__ int g_csr[MAXE];
__device__ int g_is64;

// ---------------------------------------------------------------------------
// f32x2 helpers
// ---------------------------------------------------------------------------
__device__ __forceinline__ unsigned long long fma2(unsigned long long a,
                                                   unsigned long long b,
                                                   unsigned long long c) {
    unsigned long long d;
    asm("fma.rn.f32x2 %0, %1, %2, %3;" : "=l"(d) : "l"(a), "l"(b), "l"(c));
    return d;
}
__device__ __forceinline__ unsigned long long pack2(float lo, float hi) {
    unsigned long long d;
    asm("mov.b64 %0, {%1, %2};" : "=l"(d) : "f"(lo), "f"(hi));
    return d;
}
__device__ __forceinline__ float2 unpack2(unsigned long long v) {
    float2 r;
    asm("mov.b64 {%0, %1}, %2;" : "=f"(r.x), "=f"(r.y) : "l"(v));
    return r;
}

// ---------------------------------------------------------------------------
// edge dtype probe (int64 vs int32 materialization)
// ---------------------------------------------------------------------------
__global__ void probe_init_kernel() { g_is64 = 1; }
__global__ void probe_kernel(const unsigned* __restrict__ ei) {
    int i = blockIdx.x * blockDim.x + threadIdx.x;
    if (i < 1024 && ei[2 * i + 1] != 0) atomicAnd(&g_is64, 0);
}

__device__ __forceinline__ void load_edge(const void* ei, int e, int g, int is64,
                                          int& s, int& d) {
    if (is64) {
        const long long* p = (const long long*)ei;
        s = (int)p[g];
        d = (int)p[e + g];
    } else {
        const int* p = (const int*)ei;
        s = p[g];
        d = p[e + g];
    }
}

// ---------------------------------------------------------------------------
// CSR build
// ---------------------------------------------------------------------------
__global__ void zero2_kernel(int* __restrict__ a, int* __restrict__ b, int n) {
    int i = blockIdx.x * blockDim.x + threadIdx.x;
    if (i < n) { a[i] = 0; b[i] = 0; }
}

__global__ void count_kernel(const void* __restrict__ ei, int* __restrict__ cnt,
                             int e, int n) {
    int i = blockIdx.x * blockDim.x + threadIdx.x;
    if (i >= e) return;
    int s, d;
    load_edge(ei, e, i, g_is64, s, d);
    if ((unsigned)d < (unsigned)n) atomicAdd(&cnt[d], 1);
}

__global__ void dinv_kernel(const int* __restrict__ cnt, float* __restrict__ dinv,
                            int n) {
    int i = blockIdx.x * blockDim.x + threadIdx.x;
    if (i < n) dinv[i] = rsqrtf((float)cnt[i] + 1.0f);
}

__global__ __launch_bounds__(SCAN_B) void scan_block_kernel(
    const int* __restrict__ cnt, int* __restrict__ incl, int* __restrict__ bsum,
    int n) {
    __shared__ int sm[SCAN_B];
    int i = blockIdx.x * SCAN_B + threadIdx.x;
    int v = (i < n) ? cnt[i] : 0;
    sm[threadIdx.x] = v;
    __syncthreads();
#pragma unroll
    for (int off = 1; off < SCAN_B; off <<= 1) {
        int t = (threadIdx.x >= off) ? sm[threadIdx.x - off] : 0;
        __syncthreads();
        sm[threadIdx.x] += t;
        __syncthreads();
    }
    if (i < n) incl[i] = sm[threadIdx.x];
    if (threadIdx.x == SCAN_B - 1) bsum[blockIdx.x] = sm[SCAN_B - 1];
}

__global__ __launch_bounds__(256) void scan_bsum_kernel(int* __restrict__ bsum,
                                                        int nb) {
    __shared__ int sm[256];
    int v = (threadIdx.x < nb) ? bsum[threadIdx.x] : 0;
    sm[threadIdx.x] = v;
    __syncthreads();
#pragma unroll
    for (int off = 1; off < 256; off <<= 1) {
        int t = (threadIdx.x >= off) ? sm[threadIdx.x - off] : 0;
        __syncthreads();
        sm[threadIdx.x] += t;
        __syncthreads();
    }
    if (threadIdx.x < nb) bsum[threadIdx.x] = sm[threadIdx.x] - v;
}

__global__ void scan_final_kernel(const int* __restrict__ incl,
                                  const int* __restrict__ cnt,
                                  const int* __restrict__ bsum,
                                  int* __restrict__ rowptr, int n) {
    int i = blockIdx.x * blockDim.x + threadIdx.x;
    if (i < n) rowptr[i] = incl[i] - cnt[i] + bsum[i / SCAN_B];
}

__global__ void fill_csr_kernel(const void* __restrict__ ei,
                                const int* __restrict__ rowptr,
                                int* __restrict__ fill, int* __restrict__ csr,
                                int e, int n) {
    int i = blockIdx.x * blockDim.x + threadIdx.x;
    if (i >= e) return;
    int s, d;
    load_edge(ei, e, i, g_is64, s, d);
    if ((unsigned)s >= (unsigned)n || (unsigned)d >= (unsigned)n) return;
    int pos = rowptr[d] + atomicAdd(&fill[d], 1);
    csr[pos] = s;
}

// ---------------------------------------------------------------------------
// GEMM (f32x2): H[n, COLS] = act(X[n,128]) @ W[COLS,128]^T
// thread (ti,tj) owns rows ti+16r, column pairs (2tj+32p, 2tj+32p+1)
// ---------------------------------------------------------------------------
template <int COLS, bool RELU>
__global__ __launch_bounds__(256) void gemm_kernel(
    const float* __restrict__ X, const float* __restrict__ W,
    float* __restrict__ H, int n) {
    __shared__ float xs[128][33];
    __shared__ float ws[32][130];   // [k][col], pad 2 -> float2-aligned rows

    const int t = threadIdx.x;
    const int ti = t >> 4;
    const int tj = t & 15;
    constexpr int P = COLS / 32;    // column pairs per thread
    const int row0 = blockIdx.x * 128;

    unsigned long long acc[8][P];
#pragma unroll
    for (int r = 0; r < 8; r++)
#pragma unroll
        for (int p = 0; p < P; p++) acc[r][p] = 0ull;  // bit pattern = (0.f,0.f)

    for (int kb = 0; kb < 128; kb += 32) {
        for (int idx = t; idx < 128 * 32; idx += 256) {
            int r = idx >> 5, k = idx & 31;
            int row = row0 + r;
            float v = 0.0f;
            if (row < n) {
                v = X[row * 128 + kb + k];
                if (RELU) v = fmaxf(v, 0.0f);
            }
            xs[r][k] = v;
        }
        for (int idx = t; idx < COLS * 32; idx += 256) {
            int c = idx >> 5, k = idx & 31;
            ws[k][c] = W[c * 128 + kb + k];   // transposed stage
        }
        __syncthreads();

#pragma unroll
        for (int k = 0; k < 32; k++) {
            unsigned long long xd[8];
#pragma unroll
            for (int r = 0; r < 8; r++) {
                float xv = xs[ti + 16 * r][k];
                xd[r] = pack2(xv, xv);
            }
            const unsigned long long* wrow =
                reinterpret_cast<const unsigned long long*>(&ws[k][0]);
            unsigned long long wd[P];
#pragma unroll
            for (int p = 0; p < P; p++) wd[p] = wrow[tj + 16 * p];
#pragma unroll
            for (int r = 0; r < 8; r++)
#pragma unroll
                for (int p = 0; p < P; p++) acc[r][p] = fma2(wd[p], xd[r], acc[r][p]);
        }
        __syncthreads();
    }

#pragma unroll
    for (int r = 0; r < 8; r++) {
        int row = row0 + ti + 16 * r;
        if (row < n) {
            float2* hrow = reinterpret_cast<float2*>(H + (size_t)row * COLS);
#pragma unroll
            for (int p = 0; p < P; p++) hrow[tj + 16 * p] = unpack2(acc[r][p]);
        }
    }
}

// ---------------------------------------------------------------------------
// gather (one warp per node): A[d] = b + dinv[d]^2*H[d] + sum_e dinv[s]dinv[d]H[s]
// ---------------------------------------------------------------------------
__global__ __launch_bounds__(256) void gather128_kernel(
    const int* __restrict__ csr, const int* __restrict__ rowptr,
    const int* __restrict__ cnt, const float* __restrict__ dinv,
    const float* __restrict__ H, const float* __restrict__ b,
    float* __restrict__ A, int n) {
    int warp = (blockIdx.x * blockDim.x + threadIdx.x) >> 5;
    int lane = threadIdx.x & 31;
    if (warp >= n) return;
    const int d = warp;
    const int start = rowptr[d];
    const int c = cnt[d];
    const float dd = dinv[d];

    float4 acc;
    {
        float w0 = dd * dd;
        float4 hv = reinterpret_cast<const float4*>(H + (size_t)d * 128)[lane];
        const float4 bv = reinterpret_cast<const float4*>(b)[lane];
        acc.x = bv.x + hv.x * w0;
        acc.y = bv.y + hv.y * w0;
        acc.z = bv.z + hv.z * w0;
        acc.w = bv.w + hv.w * w0;
    }

    for (int j0 = 0; j0 < c; j0 += 32) {
        int valid = j0 + lane < c;
        int s = valid ? csr[start + j0 + lane] : 0;
        float ws = valid ? dinv[s] * dd : 0.0f;
        int m = min(32, c - j0);
#pragma unroll 4
        for (int k = 0; k < m; k++) {
            int sk = __shfl_sync(0xffffffffu, s, k);
            float wk = __shfl_sync(0xffffffffu, ws, k);
            float4 v = reinterpret_cast<const float4*>(H + (size_t)sk * 128)[lane];
            acc.x = fmaf(v.x, wk, acc.x);
            acc.y = fmaf(v.y, wk, acc.y);
            acc.z = fmaf(v.z, wk, acc.z);
            acc.w = fmaf(v.w, wk, acc.w);
        }
    }
    reinterpret_cast<float4*>(A + (size_t)d * 128)[lane] = acc;
}

__global__ __launch_bounds__(256) void gather64_kernel(
    const int* __restrict__ csr, const int* __restrict__ rowptr,
    const int* __restrict__ cnt, const float* __restrict__ dinv,
    const float* __restrict__ H, const float* __restrict__ b,
    float* __restrict__ A, int n) {
    int warp = (blockIdx.x * blockDim.x + threadIdx.x) >> 5;
    int lane = threadIdx.x & 31;
    if (warp >= n) return;
    const int d = warp;
    const int start = rowptr[d];
    const int c = cnt[d];
    const float dd = dinv[d];

    float2 acc;
    {
        float w0 = dd * dd;
        float2 hv = reinterpret_cast<const float2*>(H + (size_t)d * 64)[lane];
        float2 bv = reinterpret_cast<const float2*>(b)[lane];
        acc.x = bv.x + hv.x * w0;
        acc.y = bv.y + hv.y * w0;
    }

    for (int j0 = 0; j0 < c; j0 += 32) {
        int valid = j0 + lane < c;
        int s = valid ? csr[start + j0 + lane] : 0;
        float ws = valid ? dinv[s] * dd : 0.0f;
        int m = min(32, c - j0);
#pragma unroll 4
        for (int k = 0; k < m; k++) {
            int sk = __shfl_sync(0xffffffffu, s, k);
            float wk = __shfl_sync(0xffffffffu, ws, k);
            float2 v = reinterpret_cast<const float2*>(H + (size_t)sk * 64)[lane];
            acc.x = fmaf(v.x, wk, acc.x);
            acc.y = fmaf(v.y, wk, acc.y);
        }
    }
    reinterpret_cast<float2*>(A + (size_t)d * 64)[lane] = acc;
}

// ---------------------------------------------------------------------------
// copy-out
// ---------------------------------------------------------------------------
__global__ void copy_out_kernel(float* __restrict__ out,
                                const float* __restrict__ A, int n4) {
    int i = blockIdx.x * blockDim.x + threadIdx.x;
    if (i < n4)
        reinterpret_cast<float4*>(out)[i] = reinterpret_cast<const float4*>(A)[i];
}

// ---------------------------------------------------------------------------
// launch
// ---------------------------------------------------------------------------
extern "C" void kernel_launch(void* const* d_in, const int* in_sizes, int n_in,
                              void* d_out, int out_size) {
    const float* x = (const float*)d_in[0];
    const void* ei = d_in[1];
    const float* W1 = (const float*)d_in[2];
    const float* b1 = (const float*)d_in[3];
    const float* W2 = (const float*)d_in[4];
    const float* b2 = (const float*)d_in[5];
    const float* W3 = (const float*)d_in[6];
    const float* b3 = (const float*)d_in[7];
    float* out = (float*)d_out;

    const int n = in_sizes[0] / 128;
    const int e = in_sizes[1] / 2;

    float *h, *a, *dinv;
    int *cnt, *fill, *rowptr, *incl, *bsum, *csr;
    cudaGetSymbolAddress((void**)&h, g_h);
    cudaGetSymbolAddress((void**)&a, g_a);
    cudaGetSymbolAddress((void**)&dinv, g_dinv);
    cudaGetSymbolAddress((void**)&cnt, g_cnt);
    cudaGetSymbolAddress((void**)&fill, g_fill);
    cudaGetSymbolAddress((void**)&rowptr, g_rowptr);
    cudaGetSymbolAddress((void**)&incl, g_incl);
    cudaGetSymbolAddress((void**)&bsum, g_bsum);
    cudaGetSymbolAddress((void**)&csr, g_csr);

    const int T = 256;
    const int nb = (n + SCAN_B - 1) / SCAN_B;

    probe_init_kernel<<<1, 1>>>();
    probe_kernel<<<4, 256>>>((const unsigned*)ei);

    zero2_kernel<<<(n + T - 1) / T, T>>>(cnt, fill, n);
    count_kernel<<<(e + T - 1) / T, T>>>(ei, cnt, e, n);
    dinv_kernel<<<(n + T - 1) / T, T>>>(cnt, dinv, n);
    scan_block_kernel<<<nb, SCAN_B>>>(cnt, incl, bsum, n);
    scan_bsum_kernel<<<1, 256>>>(bsum, nb);
    scan_final_kernel<<<(n + T - 1) / T, T>>>(incl, cnt, bsum, rowptr, n);
    fill_csr_kernel<<<(e + T - 1) / T, T>>>(ei, rowptr, fill, csr, e, n);

    const int gemm_blocks = (n + 127) / 128;
    const int gather_blocks = (n * 32 + T - 1) / T;

    gemm_kernel<128, false><<<gemm_blocks, 256>>>(x, W1, h, n);
    gather128_kernel<<<gather_blocks, T>>>(csr, rowptr, cnt, dinv, h, b1, a, n);

    gemm_kernel<128, true><<<gemm_blocks, 256>>>(a, W2, h, n);
    gather128_kernel<<<gather_blocks, T>>>(csr, rowptr, cnt, dinv, h, b2, a, n);

    gemm_kernel<64, true><<<gemm_blocks, 256>>>(a, W3, h, n);
    gather64_kernel<<<gather_blocks, T>>>(csr, rowptr, cnt, dinv, h, b3, a, n);
    copy_out_kernel<<<(n * 16 + T - 1) / T, T>>>(out, a, n * 16);
}

// round 8
// speedup vs baseline: 2.8094x; 1.0041x over previous
#include <cuda_runtime.h>
#include <cstdint>

// ---------------------------------------------------------------------------
// GCN 3-layer: CSR-gather + tensor-core (3xTF32 mma.sync) GEMM.
// out = GCNConv3(relu(GCNConv2(relu(GCNConv1(x)))))
// GCNConv: out = D^-1/2 (A+I) D^-1/2 (x @ W^T) + b
// N=100000, E=1600000, C: 128 -> 128 -> 128 -> 64
// ---------------------------------------------------------------------------

#define MAXN 100000
#define MAXE 1600000
#define SCAN_B 1024

__device__ __align__(16) float g_h[MAXN * 128];
__device__ __align__(16) float g_a[MAXN * 128];
__device__ float g_dinv[MAXN];
__device__ int g_cnt[MAXN];
__device__ int g_fill[MAXN];
__device__ int g_rowptr[MAXN];
__device__ int g_incl[MAXN];
__device__ int g_bsum[256];
__device__ int g_csr[MAXE];
__device__ int g_is64;

// ---------------------------------------------------------------------------
// tf32 helpers
// ---------------------------------------------------------------------------
__device__ __forceinline__ unsigned to_tf32(float f) {
    unsigned r;
    asm("cvt.rna.tf32.f32 %0, %1;" : "=r"(r) : "f"(f));
    return r;
}
__device__ __forceinline__ void cvt_hl(float v, unsigned& hi, unsigned& lo) {
    hi = to_tf32(v);
    lo = to_tf32(v - __uint_as_float(hi));
}
__device__ __forceinline__ void mma_tf32(float* c, const unsigned* a,
                                         const unsigned* b) {
    asm("mma.sync.aligned.m16n8k8.row.col.f32.tf32.tf32.f32 "
        "{%0,%1,%2,%3},{%4,%5,%6,%7},{%8,%9},{%0,%1,%2,%3};"
        : "+f"(c[0]), "+f"(c[1]), "+f"(c[2]), "+f"(c[3])
        : "r"(a[0]), "r"(a[1]), "r"(a[2]), "r"(a[3]), "r"(b[0]), "r"(b[1]));
}

// ---------------------------------------------------------------------------
// edge dtype probe (int64 vs int32 materialization)
// ---------------------------------------------------------------------------
__global__ void probe_init_kernel() { g_is64 = 1; }
__global__ void probe_kernel(const unsigned* __restrict__ ei) {
    int i = blockIdx.x * blockDim.x + threadIdx.x;
    if (i < 1024 && ei[2 * i + 1] != 0) atomicAnd(&g_is64, 0);
}

__device__ __forceinline__ void load_edge(const void* ei, int e, int g, int is64,
                                          int& s, int& d) {
    if (is64) {
        const long long* p = (const long long*)ei;
        s = (int)p[g];
        d = (int)p[e + g];
    } else {
        const int* p = (const int*)ei;
        s = p[g];
        d = p[e + g];
    }
}

// ---------------------------------------------------------------------------
// CSR build
// ---------------------------------------------------------------------------
__global__ void zero2_kernel(int* __restrict__ a, int* __restrict__ b, int n) {
    int i = blockIdx.x * blockDim.x + threadIdx.x;
    if (i < n) { a[i] = 0; b[i] = 0; }
}

__global__ void count_kernel(const void* __restrict__ ei, int* __restrict__ cnt,
                             int e, int n) {
    int i = blockIdx.x * blockDim.x + threadIdx.x;
    if (i >= e) return;
    int s, d;
    load_edge(ei, e, i, g_is64, s, d);
    if ((unsigned)d < (unsigned)n) atomicAdd(&cnt[d], 1);
}

__global__ void dinv_kernel(const int* __restrict__ cnt, float* __restrict__ dinv,
                            int n) {
    int i = blockIdx.x * blockDim.x + threadIdx.x;
    if (i < n) dinv[i] = rsqrtf((float)cnt[i] + 1.0f);
}

__global__ __launch_bounds__(SCAN_B) void scan_block_kernel(
    const int* __restrict__ cnt, int* __restrict__ incl, int* __restrict__ bsum,
    int n) {
    __shared__ int sm[SCAN_B];
    int i = blockIdx.x * SCAN_B + threadIdx.x;
    int v = (i < n) ? cnt[i] : 0;
    sm[threadIdx.x] = v;
    __syncthreads();
#pragma unroll
    for (int off = 1; off < SCAN_B; off <<= 1) {
        int t = (threadIdx.x >= off) ? sm[threadIdx.x - off] : 0;
        __syncthreads();
        sm[threadIdx.x] += t;
        __syncthreads();
    }
    if (i < n) incl[i] = sm[threadIdx.x];
    if (threadIdx.x == SCAN_B - 1) bsum[blockIdx.x] = sm[SCAN_B - 1];
}

__global__ __launch_bounds__(256) void scan_bsum_kernel(int* __restrict__ bsum,
                                                        int nb) {
    __shared__ int sm[256];
    int v = (threadIdx.x < nb) ? bsum[threadIdx.x] : 0;
    sm[threadIdx.x] = v;
    __syncthreads();
#pragma unroll
    for (int off = 1; off < 256; off <<= 1) {
        int t = (threadIdx.x >= off) ? sm[threadIdx.x - off] : 0;
        __syncthreads();
        sm[threadIdx.x] += t;
        __syncthreads();
    }
    if (threadIdx.x < nb) bsum[threadIdx.x] = sm[threadIdx.x] - v;
}

__global__ void scan_final_kernel(const int* __restrict__ incl,
                                  const int* __restrict__ cnt,
                                  const int* __restrict__ bsum,
                                  int* __restrict__ rowptr, int n) {
    int i = blockIdx.x * blockDim.x + threadIdx.x;
    if (i < n) rowptr[i] = incl[i] - cnt[i] + bsum[i / SCAN_B];
}

__global__ void fill_csr_kernel(const void* __restrict__ ei,
                                const int* __restrict__ rowptr,
                                int* __restrict__ fill, int* __restrict__ csr,
                                int e, int n) {
    int i = blockIdx.x * blockDim.x + threadIdx.x;
    if (i >= e) return;
    int s, d;
    load_edge(ei, e, i, g_is64, s, d);
    if ((unsigned)s >= (unsigned)n || (unsigned)d >= (unsigned)n) return;
    int pos = rowptr[d] + atomicAdd(&fill[d], 1);
    csr[pos] = s;
}

// ---------------------------------------------------------------------------
// Tensor-core GEMM (3xTF32): H[n, COLS] = act(X[n,128]) @ W[COLS,128]^T
// 8 warps/block. COLS=128: warp tile 32x64 (WM=2). COLS=64: 16x64 (WM=1).
// smem stride 36 -> fragment loads conflict-free (bank = 4*gid+tig).
// ---------------------------------------------------------------------------
template <int COLS, bool RELU>
__global__ __launch_bounds__(256) void gemm_tc_kernel(
    const float* __restrict__ X, const float* __restrict__ W,
    float* __restrict__ H, int n) {
    __shared__ float xs[128][36];
    __shared__ float ws[COLS][36];

    constexpr int WM = (COLS == 128) ? 2 : 1;   // m16 tiles per warp
    const int t = threadIdx.x;
    const int wid = t >> 5;
    const int lane = t & 31;
    const int gid = lane >> 2;   // 0..7
    const int tig = lane & 3;    // 0..3
    const int row0 = blockIdx.x * 128;

    int wm0, wn0;
    if (COLS == 128) { wm0 = (wid >> 1) * 32; wn0 = (wid & 1) * 64; }
    else             { wm0 = wid * 16;        wn0 = 0; }

    float acc[WM][8][4];
#pragma unroll
    for (int mt = 0; mt < WM; mt++)
#pragma unroll
        for (int nt = 0; nt < 8; nt++)
#pragma unroll
            for (int i = 0; i < 4; i++) acc[mt][nt][i] = 0.0f;

    for (int kb = 0; kb < 128; kb += 32) {
        for (int idx = t; idx < 128 * 32; idx += 256) {
            int r = idx >> 5, k = idx & 31;
            int row = row0 + r;
            float v = 0.0f;
            if (row < n) {
                v = X[row * 128 + kb + k];
                if (RELU) v = fmaxf(v, 0.0f);
            }
            xs[r][k] = v;
        }
        for (int idx = t; idx < COLS * 32; idx += 256) {
            int c = idx >> 5, k = idx & 31;
            ws[c][k] = W[c * 128 + kb + k];
        }
        __syncthreads();

#pragma unroll
        for (int ks = 0; ks < 4; ks++) {
            const int k0 = ks * 8;
            unsigned a_hi[WM][4], a_lo[WM][4];
#pragma unroll
            for (int mt = 0; mt < WM; mt++) {
                int r = wm0 + mt * 16 + gid;
                cvt_hl(xs[r][k0 + tig],         a_hi[mt][0], a_lo[mt][0]);
                cvt_hl(xs[r + 8][k0 + tig],     a_hi[mt][1], a_lo[mt][1]);
                cvt_hl(xs[r][k0 + tig + 4],     a_hi[mt][2], a_lo[mt][2]);
                cvt_hl(xs[r + 8][k0 + tig + 4], a_hi[mt][3], a_lo[mt][3]);
            }
#pragma unroll
            for (int nt = 0; nt < 8; nt++) {
                int c = wn0 + nt * 8 + gid;
                unsigned b_hi[2], b_lo[2];
                cvt_hl(ws[c][k0 + tig],     b_hi[0], b_lo[0]);
                cvt_hl(ws[c][k0 + tig + 4], b_hi[1], b_lo[1]);
#pragma unroll
                for (int mt = 0; mt < WM; mt++) {
                    mma_tf32(acc[mt][nt], a_hi[mt], b_lo);
                    mma_tf32(acc[mt][nt], a_lo[mt], b_hi);
                    mma_tf32(acc[mt][nt], a_hi[mt], b_hi);
                }
            }
        }
        __syncthreads();
    }

#pragma unroll
    for (int mt = 0; mt < WM; mt++) {
        int r = row0 + wm0 + mt * 16 + gid;
#pragma unroll
        for (int nt = 0; nt < 8; nt++) {
            int c = wn0 + nt * 8 + tig * 2;
            if (r < n)
                *reinterpret_cast<float2*>(H + (size_t)r * COLS + c) =
                    make_float2(acc[mt][nt][0], acc[mt][nt][1]);
            if (r + 8 < n)
                *reinterpret_cast<float2*>(H + (size_t)(r + 8) * COLS + c) =
                    make_float2(acc[mt][nt][2], acc[mt][nt][3]);
        }
    }
}

// ---------------------------------------------------------------------------
// gather (one warp per node): A[d] = b + dinv[d]^2*H[d] + sum_e dinv[s]dinv[d]H[s]
// ---------------------------------------------------------------------------
__global__ __launch_bounds__(256) void gather128_kernel(
    const int* __restrict__ csr, const int* __restrict__ rowptr,
    const int* __restrict__ cnt, const float* __restrict__ dinv,
    const float* __restrict__ H, const float* __restrict__ b,
    float* __restrict__ A, int n) {
    int warp = (blockIdx.x * blockDim.x + threadIdx.x) >> 5;
    int lane = threadIdx.x & 31;
    if (warp >= n) return;
    const int d = warp;
    const int start = rowptr[d];
    const int c = cnt[d];
    const float dd = dinv[d];

    float4 acc;
    {
        float w0 = dd * dd;
        float4 hv = reinterpret_cast<const float4*>(H + (size_t)d * 128)[lane];
        const float4 bv = reinterpret_cast<const float4*>(b)[lane];
        acc.x = bv.x + hv.x * w0;
        acc.y = bv.y + hv.y * w0;
        acc.z = bv.z + hv.z * w0;
        acc.w = bv.w + hv.w * w0;
    }

    for (int j0 = 0; j0 < c; j0 += 32) {
        int valid = j0 + lane < c;
        int s = valid ? csr[start + j0 + lane] : 0;
        float ws = valid ? dinv[s] * dd : 0.0f;
        int m = min(32, c - j0);
#pragma unroll 4
        for (int k = 0; k < m; k++) {
            int sk = __shfl_sync(0xffffffffu, s, k);
            float wk = __shfl_sync(0xffffffffu, ws, k);
            float4 v = reinterpret_cast<const float4*>(H + (size_t)sk * 128)[lane];
            acc.x = fmaf(v.x, wk, acc.x);
            acc.y = fmaf(v.y, wk, acc.y);
            acc.z = fmaf(v.z, wk, acc.z);
            acc.w = fmaf(v.w, wk, acc.w);
        }
    }
    reinterpret_cast<float4*>(A + (size_t)d * 128)[lane] = acc;
}

__global__ __launch_bounds__(256) void gather64_kernel(
    const int* __restrict__ csr, const int* __restrict__ rowptr,
    const int* __restrict__ cnt, const float* __restrict__ dinv,
    const float* __restrict__ H, const float* __restrict__ b,
    float* __restrict__ A, int n) {
    int warp = (blockIdx.x * blockDim.x + threadIdx.x) >> 5;
    int lane = threadIdx.x & 31;
    if (warp >= n) return;
    const int d = warp;
    const int start = rowptr[d];
    const int c = cnt[d];
    const float dd = dinv[d];

    float2 acc;
    {
        float w0 = dd * dd;
        float2 hv = reinterpret_cast<const float2*>(H + (size_t)d * 64)[lane];
        float2 bv = reinterpret_cast<const float2*>(b)[lane];
        acc.x = bv.x + hv.x * w0;
        acc.y = bv.y + hv.y * w0;
    }

    for (int j0 = 0; j0 < c; j0 += 32) {
        int valid = j0 + lane < c;
        int s = valid ? csr[start + j0 + lane] : 0;
        float ws = valid ? dinv[s] * dd : 0.0f;
        int m = min(32, c - j0);
#pragma unroll 4
        for (int k = 0; k < m; k++) {
            int sk = __shfl_sync(0xffffffffu, s, k);
            float wk = __shfl_sync(0xffffffffu, ws, k);
            float2 v = reinterpret_cast<const float2*>(H + (size_t)sk * 64)[lane];
            acc.x = fmaf(v.x, wk, acc.x);
            acc.y = fmaf(v.y, wk, acc.y);
        }
    }
    reinterpret_cast<float2*>(A + (size_t)d * 64)[lane] = acc;
}

// ---------------------------------------------------------------------------
// copy-out
// ---------------------------------------------------------------------------
__global__ void copy_out_kernel(float* __restrict__ out,
                                const float* __restrict__ A, int n4) {
    int i = blockIdx.x * blockDim.x + threadIdx.x;
    if (i < n4)
        reinterpret_cast<float4*>(out)[i] = reinterpret_cast<const float4*>(A)[i];
}

// ---------------------------------------------------------------------------
// launch
// ---------------------------------------------------------------------------
extern "C" void kernel_launch(void* const* d_in, const int* in_sizes, int n_in,
                              void* d_out, int out_size) {
    const float* x = (const float*)d_in[0];
    const void* ei = d_in[1];
    const float* W1 = (const float*)d_in[2];
    const float* b1 = (const float*)d_in[3];
    const float* W2 = (const float*)d_in[4];
    const float* b2 = (const float*)d_in[5];
    const float* W3 = (const float*)d_in[6];
    const float* b3 = (const float*)d_in[7];
    float* out = (float*)d_out;

    const int n = in_sizes[0] / 128;
    const int e = in_sizes[1] / 2;

    float *h, *a, *dinv;
    int *cnt, *fill, *rowptr, *incl, *bsum, *csr;
    cudaGetSymbolAddress((void**)&h, g_h);
    cudaGetSymbolAddress((void**)&a, g_a);
    cudaGetSymbolAddress((void**)&dinv, g_dinv);
    cudaGetSymbolAddress((void**)&cnt, g_cnt);
    cudaGetSymbolAddress((void**)&fill, g_fill);
    cudaGetSymbolAddress((void**)&rowptr, g_rowptr);
    cudaGetSymbolAddress((void**)&incl, g_incl);
    cudaGetSymbolAddress((void**)&bsum, g_bsum);
    cudaGetSymbolAddress((void**)&csr, g_csr);

    const int T = 256;
    const int nb = (n + SCAN_B - 1) / SCAN_B;

    probe_init_kernel<<<1, 1>>>();
    probe_kernel<<<4, 256>>>((const unsigned*)ei);

    zero2_kernel<<<(n + T - 1) / T, T>>>(cnt, fill, n);
    count_kernel<<<(e + T - 1) / T, T>>>(ei, cnt, e, n);
    dinv_kernel<<<(n + T - 1) / T, T>>>(cnt, dinv, n);
    scan_block_kernel<<<nb, SCAN_B>>>(cnt, incl, bsum, n);
    scan_bsum_kernel<<<1, 256>>>(bsum, nb);
    scan_final_kernel<<<(n + T - 1) / T, T>>>(incl, cnt, bsum, rowptr, n);
    fill_csr_kernel<<<(e + T - 1) / T, T>>>(ei, rowptr, fill, csr, e, n);

    const int gemm_blocks = (n + 127) / 128;
    const int gather_blocks = (n * 32 + T - 1) / T;

    gemm_tc_kernel<128, false><<<gemm_blocks, 256>>>(x, W1, h, n);
    gather128_kernel<<<gather_blocks, T>>>(csr, rowptr, cnt, dinv, h, b1, a, n);

    gemm_tc_kernel<128, true><<<gemm_blocks, 256>>>(a, W2, h, n);
    gather128_kernel<<<gather_blocks, T>>>(csr, rowptr, cnt, dinv, h, b2, a, n);

    gemm_tc_kernel<64, true><<<gemm_blocks, 256>>>(a, W3, h, n);
    gather64_kernel<<<gather_blocks, T>>>(csr, rowptr, cnt, dinv, h, b3, a, n);
    copy_out_kernel<<<(n * 16 + T - 1) / T, T>>>(out, a, n * 16);
}

// round 9
// speedup vs baseline: 2.8974x; 1.0313x over previous
#include <cuda_runtime.h>
#include <cstdint>

// ---------------------------------------------------------------------------
// GCN 3-layer: CSR-gather (deep-MLP) + tensor-core (3xTF32 mma.sync) GEMM.
// out = GCNConv3(relu(GCNConv2(relu(GCNConv1(x)))))
// GCNConv: out = D^-1/2 (A+I) D^-1/2 (x @ W^T) + b
// N=100000, E=1600000, C: 128 -> 128 -> 128 -> 64
// ---------------------------------------------------------------------------

#define MAXN 100000
#define MAXE 1600000
#define SCAN_B 1024

__device__ __align__(16) float g_h[MAXN * 128];
__device__ __align__(16) float g_a[MAXN * 128];
__device__ float g_dinv[MAXN];
__device__ int g_cnt[MAXN];
__device__ int g_fill[MAXN];
__device__ int g_rowptr[MAXN];
__device__ int g_incl[MAXN];
__device__ int g_bsum[256];
__device__ int g_csr[MAXE];
__device__ int g_is64;

// ---------------------------------------------------------------------------
// tf32 helpers
// ---------------------------------------------------------------------------
__device__ __forceinline__ unsigned to_tf32(float f) {
    unsigned r;
    asm("cvt.rna.tf32.f32 %0, %1;" : "=r"(r) : "f"(f));
    return r;
}
__device__ __forceinline__ void cvt_hl(float v, unsigned& hi, unsigned& lo) {
    hi = to_tf32(v);
    lo = to_tf32(v - __uint_as_float(hi));
}
__device__ __forceinline__ void mma_tf32(float* c, const unsigned* a,
                                         const unsigned* b) {
    asm("mma.sync.aligned.m16n8k8.row.col.f32.tf32.tf32.f32 "
        "{%0,%1,%2,%3},{%4,%5,%6,%7},{%8,%9},{%0,%1,%2,%3};"
        : "+f"(c[0]), "+f"(c[1]), "+f"(c[2]), "+f"(c[3])
        : "r"(a[0]), "r"(a[1]), "r"(a[2]), "r"(a[3]), "r"(b[0]), "r"(b[1]));
}

// ---------------------------------------------------------------------------
// edge dtype probe (int64 vs int32 materialization)
// ---------------------------------------------------------------------------
__global__ void probe_init_kernel() { g_is64 = 1; }
__global__ void probe_kernel(const unsigned* __restrict__ ei) {
    int i = blockIdx.x * blockDim.x + threadIdx.x;
    if (i < 1024 && ei[2 * i + 1] != 0) atomicAnd(&g_is64, 0);
}

__device__ __forceinline__ void load_edge(const void* ei, int e, int g, int is64,
                                          int& s, int& d) {
    if (is64) {
        const long long* p = (const long long*)ei;
        s = (int)p[g];
        d = (int)p[e + g];
    } else {
        const int* p = (const int*)ei;
        s = p[g];
        d = p[e + g];
    }
}

// ---------------------------------------------------------------------------
// CSR build
// ---------------------------------------------------------------------------
__global__ void zero1_kernel(int* __restrict__ a, int n) {
    int i = blockIdx.x * blockDim.x + threadIdx.x;
    if (i < n) a[i] = 0;
}

__global__ void count_kernel(const void* __restrict__ ei, int* __restrict__ cnt,
                             int e, int n) {
    int i = blockIdx.x * blockDim.x + threadIdx.x;
    if (i >= e) return;
    int s, d;
    load_edge(ei, e, i, g_is64, s, d);
    if ((unsigned)d < (unsigned)n) atomicAdd(&cnt[d], 1);
}

__global__ void dinv_kernel(const int* __restrict__ cnt, float* __restrict__ dinv,
                            int n) {
    int i = blockIdx.x * blockDim.x + threadIdx.x;
    if (i < n) dinv[i] = rsqrtf((float)cnt[i] + 1.0f);
}

__global__ __launch_bounds__(SCAN_B) void scan_block_kernel(
    const int* __restrict__ cnt, int* __restrict__ incl, int* __restrict__ bsum,
    int n) {
    __shared__ int sm[SCAN_B];
    int i = blockIdx.x * SCAN_B + threadIdx.x;
    int v = (i < n) ? cnt[i] : 0;
    sm[threadIdx.x] = v;
    __syncthreads();
#pragma unroll
    for (int off = 1; off < SCAN_B; off <<= 1) {
        int t = (threadIdx.x >= off) ? sm[threadIdx.x - off] : 0;
        __syncthreads();
        sm[threadIdx.x] += t;
        __syncthreads();
    }
    if (i < n) incl[i] = sm[threadIdx.x];
    if (threadIdx.x == SCAN_B - 1) bsum[blockIdx.x] = sm[SCAN_B - 1];
}

__global__ __launch_bounds__(256) void scan_bsum_kernel(int* __restrict__ bsum,
                                                        int nb) {
    __shared__ int sm[256];
    int v = (threadIdx.x < nb) ? bsum[threadIdx.x] : 0;
    sm[threadIdx.x] = v;
    __syncthreads();
#pragma unroll
    for (int off = 1; off < 256; off <<= 1) {
        int t = (threadIdx.x >= off) ? sm[threadIdx.x - off] : 0;
        __syncthreads();
        sm[threadIdx.x] += t;
        __syncthreads();
    }
    if (threadIdx.x < nb) bsum[threadIdx.x] = sm[threadIdx.x] - v;
}

__global__ void scan_final_kernel(const int* __restrict__ incl,
                                  const int* __restrict__ cnt,
                                  const int* __restrict__ bsum,
                                  int* __restrict__ rowptr,
                                  int* __restrict__ fill, int n) {
    int i = blockIdx.x * blockDim.x + threadIdx.x;
    if (i < n) {
        int rp = incl[i] - cnt[i] + bsum[i / SCAN_B];
        rowptr[i] = rp;
        fill[i] = rp;   // fill cursor starts at row start
    }
}

__global__ void fill_csr_kernel(const void* __restrict__ ei,
                                int* __restrict__ fill, int* __restrict__ csr,
                                int e, int n) {
    int i = blockIdx.x * blockDim.x + threadIdx.x;
    if (i >= e) return;
    int s, d;
    load_edge(ei, e, i, g_is64, s, d);
    if ((unsigned)s >= (unsigned)n || (unsigned)d >= (unsigned)n) return;
    int pos = atomicAdd(&fill[d], 1);
    csr[pos] = s;
}

// ---------------------------------------------------------------------------
// Tensor-core GEMM (3xTF32): H[n, COLS] = act(X[n,128]) @ W[COLS,128]^T
// ---------------------------------------------------------------------------
template <int COLS, bool RELU>
__global__ __launch_bounds__(256) void gemm_tc_kernel(
    const float* __restrict__ X, const float* __restrict__ W,
    float* __restrict__ H, int n) {
    __shared__ float xs[128][36];
    __shared__ float ws[COLS][36];

    constexpr int WM = (COLS == 128) ? 2 : 1;
    const int t = threadIdx.x;
    const int wid = t >> 5;
    const int lane = t & 31;
    const int gid = lane >> 2;
    const int tig = lane & 3;
    const int row0 = blockIdx.x * 128;

    int wm0, wn0;
    if (COLS == 128) { wm0 = (wid >> 1) * 32; wn0 = (wid & 1) * 64; }
    else             { wm0 = wid * 16;        wn0 = 0; }

    float acc[WM][8][4];
#pragma unroll
    for (int mt = 0; mt < WM; mt++)
#pragma unroll
        for (int nt = 0; nt < 8; nt++)
#pragma unroll
            for (int i = 0; i < 4; i++) acc[mt][nt][i] = 0.0f;

    for (int kb = 0; kb < 128; kb += 32) {
        for (int idx = t; idx < 128 * 32; idx += 256) {
            int r = idx >> 5, k = idx & 31;
            int row = row0 + r;
            float v = 0.0f;
            if (row < n) {
                v = X[row * 128 + kb + k];
                if (RELU) v = fmaxf(v, 0.0f);
            }
            xs[r][k] = v;
        }
        for (int idx = t; idx < COLS * 32; idx += 256) {
            int c = idx >> 5, k = idx & 31;
            ws[c][k] = W[c * 128 + kb + k];
        }
        __syncthreads();

#pragma unroll
        for (int ks = 0; ks < 4; ks++) {
            const int k0 = ks * 8;
            unsigned a_hi[WM][4], a_lo[WM][4];
#pragma unroll
            for (int mt = 0; mt < WM; mt++) {
                int r = wm0 + mt * 16 + gid;
                cvt_hl(xs[r][k0 + tig],         a_hi[mt][0], a_lo[mt][0]);
                cvt_hl(xs[r + 8][k0 + tig],     a_hi[mt][1], a_lo[mt][1]);
                cvt_hl(xs[r][k0 + tig + 4],     a_hi[mt][2], a_lo[mt][2]);
                cvt_hl(xs[r + 8][k0 + tig + 4], a_hi[mt][3], a_lo[mt][3]);
            }
#pragma unroll
            for (int nt = 0; nt < 8; nt++) {
                int c = wn0 + nt * 8 + gid;
                unsigned b_hi[2], b_lo[2];
                cvt_hl(ws[c][k0 + tig],     b_hi[0], b_lo[0]);
                cvt_hl(ws[c][k0 + tig + 4], b_hi[1], b_lo[1]);
#pragma unroll
                for (int mt = 0; mt < WM; mt++) {
                    mma_tf32(acc[mt][nt], a_hi[mt], b_lo);
                    mma_tf32(acc[mt][nt], a_lo[mt], b_hi);
                    mma_tf32(acc[mt][nt], a_hi[mt], b_hi);
                }
            }
        }
        __syncthreads();
    }

#pragma unroll
    for (int mt = 0; mt < WM; mt++) {
        int r = row0 + wm0 + mt * 16 + gid;
#pragma unroll
        for (int nt = 0; nt < 8; nt++) {
            int c = wn0 + nt * 8 + tig * 2;
            if (r < n)
                *reinterpret_cast<float2*>(H + (size_t)r * COLS + c) =
                    make_float2(acc[mt][nt][0], acc[mt][nt][1]);
            if (r + 8 < n)
                *reinterpret_cast<float2*>(H + (size_t)(r + 8) * COLS + c) =
                    make_float2(acc[mt][nt][2], acc[mt][nt][3]);
        }
    }
}

// ---------------------------------------------------------------------------
// gather (one warp per node), deep-MLP (unroll 8):
// A[d] = b + dinv[d]^2*H[d] + sum_e dinv[s]dinv[d]H[s]
// ---------------------------------------------------------------------------
__global__ __launch_bounds__(256) void gather128_kernel(
    const int* __restrict__ csr, const int* __restrict__ rowptr,
    const int* __restrict__ cnt, const float* __restrict__ dinv,
    const float* __restrict__ H, const float* __restrict__ b,
    float* __restrict__ A, int n) {
    int warp = (blockIdx.x * blockDim.x + threadIdx.x) >> 5;
    int lane = threadIdx.x & 31;
    if (warp >= n) return;
    const int d = warp;
    const int start = rowptr[d];
    const int c = cnt[d];
    const float dd = dinv[d];

    float4 acc;
    {
        float w0 = dd * dd;
        float4 hv = reinterpret_cast<const float4*>(H + (size_t)d * 128)[lane];
        const float4 bv = reinterpret_cast<const float4*>(b)[lane];
        acc.x = bv.x + hv.x * w0;
        acc.y = bv.y + hv.y * w0;
        acc.z = bv.z + hv.z * w0;
        acc.w = bv.w + hv.w * w0;
    }

    for (int j0 = 0; j0 < c; j0 += 32) {
        int valid = j0 + lane < c;
        int s = valid ? csr[start + j0 + lane] : 0;
        float ws = valid ? dinv[s] * dd : 0.0f;
        int m = min(32, c - j0);
#pragma unroll 8
        for (int k = 0; k < m; k++) {
            int sk = __shfl_sync(0xffffffffu, s, k);
            float wk = __shfl_sync(0xffffffffu, ws, k);
            float4 v = reinterpret_cast<const float4*>(H + (size_t)sk * 128)[lane];
            acc.x = fmaf(v.x, wk, acc.x);
            acc.y = fmaf(v.y, wk, acc.y);
            acc.z = fmaf(v.z, wk, acc.z);
            acc.w = fmaf(v.w, wk, acc.w);
        }
    }
    reinterpret_cast<float4*>(A + (size_t)d * 128)[lane] = acc;
}

__global__ __launch_bounds__(256) void gather64_kernel(
    const int* __restrict__ csr, const int* __restrict__ rowptr,
    const int* __restrict__ cnt, const float* __restrict__ dinv,
    const float* __restrict__ H, const float* __restrict__ b,
    float* __restrict__ A, int n) {
    int warp = (blockIdx.x * blockDim.x + threadIdx.x) >> 5;
    int lane = threadIdx.x & 31;
    if (warp >= n) return;
    const int d = warp;
    const int start = rowptr[d];
    const int c = cnt[d];
    const float dd = dinv[d];

    float2 acc;
    {
        float w0 = dd * dd;
        float2 hv = reinterpret_cast<const float2*>(H + (size_t)d * 64)[lane];
        float2 bv = reinterpret_cast<const float2*>(b)[lane];
        acc.x = bv.x + hv.x * w0;
        acc.y = bv.y + hv.y * w0;
    }

    for (int j0 = 0; j0 < c; j0 += 32) {
        int valid = j0 + lane < c;
        int s = valid ? csr[start + j0 + lane] : 0;
        float ws = valid ? dinv[s] * dd : 0.0f;
        int m = min(32, c - j0);
#pragma unroll 8
        for (int k = 0; k < m; k++) {
            int sk = __shfl_sync(0xffffffffu, s, k);
            float wk = __shfl_sync(0xffffffffu, ws, k);
            float2 v = reinterpret_cast<const float2*>(H + (size_t)sk * 64)[lane];
            acc.x = fmaf(v.x, wk, acc.x);
            acc.y = fmaf(v.y, wk, acc.y);
        }
    }
    reinterpret_cast<float2*>(A + (size_t)d * 64)[lane] = acc;
}

// ---------------------------------------------------------------------------
// launch
// ---------------------------------------------------------------------------
extern "C" void kernel_launch(void* const* d_in, const int* in_sizes, int n_in,
                              void* d_out, int out_size) {
    const float* x = (const float*)d_in[0];
    const void* ei = d_in[1];
    const float* W1 = (const float*)d_in[2];
    const float* b1 = (const float*)d_in[3];
    const float* W2 = (const float*)d_in[4];
    const float* b2 = (const float*)d_in[5];
    const float* W3 = (const float*)d_in[6];
    const float* b3 = (const float*)d_in[7];
    float* out = (float*)d_out;

    const int n = in_sizes[0] / 128;
    const int e = in_sizes[1] / 2;

    float *h, *a, *dinv;
    int *cnt, *fill, *rowptr, *incl, *bsum, *csr;
    cudaGetSymbolAddress((void**)&h, g_h);
    cudaGetSymbolAddress((void**)&a, g_a);
    cudaGetSymbolAddress((void**)&dinv, g_dinv);
    cudaGetSymbolAddress((void**)&cnt, g_cnt);
    cudaGetSymbolAddress((void**)&fill, g_fill);
    cudaGetSymbolAddress((void**)&rowptr, g_rowptr);
    cudaGetSymbolAddress((void**)&incl, g_incl);
    cudaGetSymbolAddress((void**)&bsum, g_bsum);
    cudaGetSymbolAddress((void**)&csr, g_csr);

    const int T = 256;
    const int nb = (n + SCAN_B - 1) / SCAN_B;

    probe_init_kernel<<<1, 1>>>();
    probe_kernel<<<4, 256>>>((const unsigned*)ei);

    zero1_kernel<<<(n + T - 1) / T, T>>>(cnt, n);
    count_kernel<<<(e + T - 1) / T, T>>>(ei, cnt, e, n);
    dinv_kernel<<<(n + T - 1) / T, T>>>(cnt, dinv, n);
    scan_block_kernel<<<nb, SCAN_B>>>(cnt, incl, bsum, n);
    scan_bsum_kernel<<<1, 256>>>(bsum, nb);
    scan_final_kernel<<<(n + T - 1) / T, T>>>(incl, cnt, bsum, rowptr, fill, n);
    fill_csr_kernel<<<(e + T - 1) / T, T>>>(ei, fill, csr, e, n);

    const int gemm_blocks = (n + 127) / 128;
    const int gather_blocks = (n * 32 + T - 1) / T;

    gemm_tc_kernel<128, false><<<gemm_blocks, 256>>>(x, W1, h, n);
    gather128_kernel<<<gather_blocks, T>>>(csr, rowptr, cnt, dinv, h, b1, a, n);

    gemm_tc_kernel<128, true><<<gemm_blocks, 256>>>(a, W2, h, n);
    gather128_kernel<<<gather_blocks, T>>>(csr, rowptr, cnt, dinv, h, b2, a, n);

    gemm_tc_kernel<64, true><<<gemm_blocks, 256>>>(a, W3, h, n);
    // final gather writes d_out directly (plain stores, no copy kernel)
    gather64_kernel<<<gather_blocks, T>>>(csr, rowptr, cnt, dinv, h, b3, out, n);
}

// round 10
// speedup vs baseline: 3.3704x; 1.1632x over previous
#include <cuda_runtime.h>
#include <cuda_fp16.h>
#include <cstdint>

// ---------------------------------------------------------------------------
// GCN 3-layer: CSR-gather over fp16 feature rows + tensor-core (3xTF32) GEMM.
// out = GCNConv3(relu(GCNConv2(relu(GCNConv1(x)))))
// GCNConv: out = D^-1/2 (A+I) D^-1/2 (x @ W^T) + b
// N=100000, E=1600000, C: 128 -> 128 -> 128 -> 64
//
// Gathers are L2-BW bound (R9 evidence): halve their read stream by storing
// the GEMM output H in fp16. Accumulation and GEMM inputs remain fp32.
// ---------------------------------------------------------------------------

#define MAXN 100000
#define MAXE 1600000
#define SCAN_B 1024

__device__ __align__(16) __half g_h16[MAXN * 128];  // GEMM out (fp16 rows)
__device__ __align__(16) float g_a[MAXN * 128];     // gather accumulator (fp32)
__device__ float g_dinv[MAXN];
__device__ int g_cnt[MAXN];
__device__ int g_fill[MAXN];
__device__ int g_rowptr[MAXN];
__device__ int g_incl[MAXN];
__device__ int g_bsum[256];
__device__ int g_csr[MAXE];
__device__ int g_is64;

// ---------------------------------------------------------------------------
// tf32 helpers
// ---------------------------------------------------------------------------
__device__ __forceinline__ unsigned to_tf32(float f) {
    unsigned r;
    asm("cvt.rna.tf32.f32 %0, %1;" : "=r"(r) : "f"(f));
    return r;
}
__device__ __forceinline__ void cvt_hl(float v, unsigned& hi, unsigned& lo) {
    hi = to_tf32(v);
    lo = to_tf32(v - __uint_as_float(hi));
}
__device__ __forceinline__ void mma_tf32(float* c, const unsigned* a,
                                         const unsigned* b) {
    asm("mma.sync.aligned.m16n8k8.row.col.f32.tf32.tf32.f32 "
        "{%0,%1,%2,%3},{%4,%5,%6,%7},{%8,%9},{%0,%1,%2,%3};"
        : "+f"(c[0]), "+f"(c[1]), "+f"(c[2]), "+f"(c[3])
        : "r"(a[0]), "r"(a[1]), "r"(a[2]), "r"(a[3]), "r"(b[0]), "r"(b[1]));
}

// ---------------------------------------------------------------------------
// edge dtype probe (int64 vs int32 materialization)
// ---------------------------------------------------------------------------
__global__ void probe_init_kernel() { g_is64 = 1; }
__global__ void probe_kernel(const unsigned* __restrict__ ei) {
    int i = blockIdx.x * blockDim.x + threadIdx.x;
    if (i < 1024 && ei[2 * i + 1] != 0) atomicAnd(&g_is64, 0);
}

__device__ __forceinline__ void load_edge(const void* ei, int e, int g, int is64,
                                          int& s, int& d) {
    if (is64) {
        const long long* p = (const long long*)ei;
        s = (int)p[g];
        d = (int)p[e + g];
    } else {
        const int* p = (const int*)ei;
        s = p[g];
        d = p[e + g];
    }
}

// ---------------------------------------------------------------------------
// CSR build
// ---------------------------------------------------------------------------
__global__ void zero1_kernel(int* __restrict__ a, int n) {
    int i = blockIdx.x * blockDim.x + threadIdx.x;
    if (i < n) a[i] = 0;
}

__global__ void count_kernel(const void* __restrict__ ei, int* __restrict__ cnt,
                             int e, int n) {
    int i = blockIdx.x * blockDim.x + threadIdx.x;
    if (i >= e) return;
    int s, d;
    load_edge(ei, e, i, g_is64, s, d);
    if ((unsigned)d < (unsigned)n) atomicAdd(&cnt[d], 1);
}

__global__ void dinv_kernel(const int* __restrict__ cnt, float* __restrict__ dinv,
                            int n) {
    int i = blockIdx.x * blockDim.x + threadIdx.x;
    if (i < n) dinv[i] = rsqrtf((float)cnt[i] + 1.0f);
}

__global__ __launch_bounds__(SCAN_B) void scan_block_kernel(
    const int* __restrict__ cnt, int* __restrict__ incl, int* __restrict__ bsum,
    int n) {
    __shared__ int sm[SCAN_B];
    int i = blockIdx.x * SCAN_B + threadIdx.x;
    int v = (i < n) ? cnt[i] : 0;
    sm[threadIdx.x] = v;
    __syncthreads();
#pragma unroll
    for (int off = 1; off < SCAN_B; off <<= 1) {
        int t = (threadIdx.x >= off) ? sm[threadIdx.x - off] : 0;
        __syncthreads();
        sm[threadIdx.x] += t;
        __syncthreads();
    }
    if (i < n) incl[i] = sm[threadIdx.x];
    if (threadIdx.x == SCAN_B - 1) bsum[blockIdx.x] = sm[SCAN_B - 1];
}

__global__ __launch_bounds__(256) void scan_bsum_kernel(int* __restrict__ bsum,
                                                        int nb) {
    __shared__ int sm[256];
    int v = (threadIdx.x < nb) ? bsum[threadIdx.x] : 0;
    sm[threadIdx.x] = v;
    __syncthreads();
#pragma unroll
    for (int off = 1; off < 256; off <<= 1) {
        int t = (threadIdx.x >= off) ? sm[threadIdx.x - off] : 0;
        __syncthreads();
        sm[threadIdx.x] += t;
        __syncthreads();
    }
    if (threadIdx.x < nb) bsum[threadIdx.x] = sm[threadIdx.x] - v;
}

__global__ void scan_final_kernel(const int* __restrict__ incl,
                                  const int* __restrict__ cnt,
                                  const int* __restrict__ bsum,
                                  int* __restrict__ rowptr,
                                  int* __restrict__ fill, int n) {
    int i = blockIdx.x * blockDim.x + threadIdx.x;
    if (i < n) {
        int rp = incl[i] - cnt[i] + bsum[i / SCAN_B];
        rowptr[i] = rp;
        fill[i] = rp;
    }
}

__global__ void fill_csr_kernel(const void* __restrict__ ei,
                                int* __restrict__ fill, int* __restrict__ csr,
                                int e, int n) {
    int i = blockIdx.x * blockDim.x + threadIdx.x;
    if (i >= e) return;
    int s, d;
    load_edge(ei, e, i, g_is64, s, d);
    if ((unsigned)s >= (unsigned)n || (unsigned)d >= (unsigned)n) return;
    int pos = atomicAdd(&fill[d], 1);
    csr[pos] = s;
}

// ---------------------------------------------------------------------------
// Tensor-core GEMM (3xTF32): H16[n, COLS] = fp16(act(X[n,128]) @ W[COLS,128]^T)
// ---------------------------------------------------------------------------
template <int COLS, bool RELU>
__global__ __launch_bounds__(256) void gemm_tc_kernel(
    const float* __restrict__ X, const float* __restrict__ W,
    __half* __restrict__ H, int n) {
    __shared__ float xs[128][36];
    __shared__ float ws[COLS][36];

    constexpr int WM = (COLS == 128) ? 2 : 1;
    const int t = threadIdx.x;
    const int wid = t >> 5;
    const int lane = t & 31;
    const int gid = lane >> 2;
    const int tig = lane & 3;
    const int row0 = blockIdx.x * 128;

    int wm0, wn0;
    if (COLS == 128) { wm0 = (wid >> 1) * 32; wn0 = (wid & 1) * 64; }
    else             { wm0 = wid * 16;        wn0 = 0; }

    float acc[WM][8][4];
#pragma unroll
    for (int mt = 0; mt < WM; mt++)
#pragma unroll
        for (int nt = 0; nt < 8; nt++)
#pragma unroll
            for (int i = 0; i < 4; i++) acc[mt][nt][i] = 0.0f;

    for (int kb = 0; kb < 128; kb += 32) {
        for (int idx = t; idx < 128 * 32; idx += 256) {
            int r = idx >> 5, k = idx & 31;
            int row = row0 + r;
            float v = 0.0f;
            if (row < n) {
                v = X[row * 128 + kb + k];
                if (RELU) v = fmaxf(v, 0.0f);
            }
            xs[r][k] = v;
        }
        for (int idx = t; idx < COLS * 32; idx += 256) {
            int c = idx >> 5, k = idx & 31;
            ws[c][k] = W[c * 128 + kb + k];
        }
        __syncthreads();

#pragma unroll
        for (int ks = 0; ks < 4; ks++) {
            const int k0 = ks * 8;
            unsigned a_hi[WM][4], a_lo[WM][4];
#pragma unroll
            for (int mt = 0; mt < WM; mt++) {
                int r = wm0 + mt * 16 + gid;
                cvt_hl(xs[r][k0 + tig],         a_hi[mt][0], a_lo[mt][0]);
                cvt_hl(xs[r + 8][k0 + tig],     a_hi[mt][1], a_lo[mt][1]);
                cvt_hl(xs[r][k0 + tig + 4],     a_hi[mt][2], a_lo[mt][2]);
                cvt_hl(xs[r + 8][k0 + tig + 4], a_hi[mt][3], a_lo[mt][3]);
            }
#pragma unroll
            for (int nt = 0; nt < 8; nt++) {
                int c = wn0 + nt * 8 + gid;
                unsigned b_hi[2], b_lo[2];
                cvt_hl(ws[c][k0 + tig],     b_hi[0], b_lo[0]);
                cvt_hl(ws[c][k0 + tig + 4], b_hi[1], b_lo[1]);
#pragma unroll
                for (int mt = 0; mt < WM; mt++) {
                    mma_tf32(acc[mt][nt], a_hi[mt], b_lo);
                    mma_tf32(acc[mt][nt], a_lo[mt], b_hi);
                    mma_tf32(acc[mt][nt], a_hi[mt], b_hi);
                }
            }
        }
        __syncthreads();
    }

#pragma unroll
    for (int mt = 0; mt < WM; mt++) {
        int r = row0 + wm0 + mt * 16 + gid;
#pragma unroll
        for (int nt = 0; nt < 8; nt++) {
            int c = wn0 + nt * 8 + tig * 2;
            if (r < n)
                *reinterpret_cast<__half2*>(H + (size_t)r * COLS + c) =
                    __floats2half2_rn(acc[mt][nt][0], acc[mt][nt][1]);
            if (r + 8 < n)
                *reinterpret_cast<__half2*>(H + (size_t)(r + 8) * COLS + c) =
                    __floats2half2_rn(acc[mt][nt][2], acc[mt][nt][3]);
        }
    }
}

// ---------------------------------------------------------------------------
// gather (one warp per node), fp16 source rows, fp32 accumulate:
// A[d] = b + dinv[d]^2*H[d] + sum_e dinv[s]dinv[d]H[s]
// ---------------------------------------------------------------------------
__global__ __launch_bounds__(256) void gather128_kernel(
    const int* __restrict__ csr, const int* __restrict__ rowptr,
    const int* __restrict__ cnt, const float* __restrict__ dinv,
    const __half* __restrict__ H, const float* __restrict__ b,
    float* __restrict__ A, int n) {
    int warp = (blockIdx.x * blockDim.x + threadIdx.x) >> 5;
    int lane = threadIdx.x & 31;
    if (warp >= n) return;
    const int d = warp;
    const int start = rowptr[d];
    const int c = cnt[d];
    const float dd = dinv[d];

    float4 acc;
    {
        float w0 = dd * dd;
        uint2 u = reinterpret_cast<const uint2*>(H + (size_t)d * 128)[lane];
        float2 lo = __half22float2(*reinterpret_cast<__half2*>(&u.x));
        float2 hi = __half22float2(*reinterpret_cast<__half2*>(&u.y));
        const float4 bv = reinterpret_cast<const float4*>(b)[lane];
        acc.x = bv.x + lo.x * w0;
        acc.y = bv.y + lo.y * w0;
        acc.z = bv.z + hi.x * w0;
        acc.w = bv.w + hi.y * w0;
    }

    for (int j0 = 0; j0 < c; j0 += 32) {
        int valid = j0 + lane < c;
        int s = valid ? csr[start + j0 + lane] : 0;
        float ws = valid ? dinv[s] * dd : 0.0f;
        int m = min(32, c - j0);
#pragma unroll 8
        for (int k = 0; k < m; k++) {
            int sk = __shfl_sync(0xffffffffu, s, k);
            float wk = __shfl_sync(0xffffffffu, ws, k);
            uint2 u = reinterpret_cast<const uint2*>(H + (size_t)sk * 128)[lane];
            float2 lo = __half22float2(*reinterpret_cast<__half2*>(&u.x));
            float2 hi = __half22float2(*reinterpret_cast<__half2*>(&u.y));
            acc.x = fmaf(lo.x, wk, acc.x);
            acc.y = fmaf(lo.y, wk, acc.y);
            acc.z = fmaf(hi.x, wk, acc.z);
            acc.w = fmaf(hi.y, wk, acc.w);
        }
    }
    // interleave back: lane owns channels 4*lane..4*lane+3
    reinterpret_cast<float4*>(A + (size_t)d * 128)[lane] = acc;
}

__global__ __launch_bounds__(256) void gather64_kernel(
    const int* __restrict__ csr, const int* __restrict__ rowptr,
    const int* __restrict__ cnt, const float* __restrict__ dinv,
    const __half* __restrict__ H, const float* __restrict__ b,
    float* __restrict__ A, int n) {
    int warp = (blockIdx.x * blockDim.x + threadIdx.x) >> 5;
    int lane = threadIdx.x & 31;
    if (warp >= n) return;
    const int d = warp;
    const int start = rowptr[d];
    const int c = cnt[d];
    const float dd = dinv[d];

    float2 acc;
    {
        float w0 = dd * dd;
        unsigned u = reinterpret_cast<const unsigned*>(H + (size_t)d * 64)[lane];
        float2 hv = __half22float2(*reinterpret_cast<__half2*>(&u));
        float2 bv = reinterpret_cast<const float2*>(b)[lane];
        acc.x = bv.x + hv.x * w0;
        acc.y = bv.y + hv.y * w0;
    }

    for (int j0 = 0; j0 < c; j0 += 32) {
        int valid = j0 + lane < c;
        int s = valid ? csr[start + j0 + lane] : 0;
        float ws = valid ? dinv[s] * dd : 0.0f;
        int m = min(32, c - j0);
#pragma unroll 8
        for (int k = 0; k < m; k++) {
            int sk = __shfl_sync(0xffffffffu, s, k);
            float wk = __shfl_sync(0xffffffffu, ws, k);
            unsigned u = reinterpret_cast<const unsigned*>(H + (size_t)sk * 64)[lane];
            float2 v = __half22float2(*reinterpret_cast<__half2*>(&u));
            acc.x = fmaf(v.x, wk, acc.x);
            acc.y = fmaf(v.y, wk, acc.y);
        }
    }
    reinterpret_cast<float2*>(A + (size_t)d * 64)[lane] = acc;
}

// ---------------------------------------------------------------------------
// launch
// ---------------------------------------------------------------------------
extern "C" void kernel_launch(void* const* d_in, const int* in_sizes, int n_in,
                              void* d_out, int out_size) {
    const float* x = (const float*)d_in[0];
    const void* ei = d_in[1];
    const float* W1 = (const float*)d_in[2];
    const float* b1 = (const float*)d_in[3];
    const float* W2 = (const float*)d_in[4];
    const float* b2 = (const float*)d_in[5];
    const float* W3 = (const float*)d_in[6];
    const float* b3 = (const float*)d_in[7];
    float* out = (float*)d_out;

    const int n = in_sizes[0] / 128;
    const int e = in_sizes[1] / 2;

    __half* h16;
    float *a, *dinv;
    int *cnt, *fill, *rowptr, *incl, *bsum, *csr;
    cudaGetSymbolAddress((void**)&h16, g_h16);
    cudaGetSymbolAddress((void**)&a, g_a);
    cudaGetSymbolAddress((void**)&dinv, g_dinv);
    cudaGetSymbolAddress((void**)&cnt, g_cnt);
    cudaGetSymbolAddress((void**)&fill, g_fill);
    cudaGetSymbolAddress((void**)&rowptr, g_rowptr);
    cudaGetSymbolAddress((void**)&incl, g_incl);
    cudaGetSymbolAddress((void**)&bsum, g_bsum);
    cudaGetSymbolAddress((void**)&csr, g_csr);

    const int T = 256;
    const int nb = (n + SCAN_B - 1) / SCAN_B;

    probe_init_kernel<<<1, 1>>>();
    probe_kernel<<<4, 256>>>((const unsigned*)ei);

    zero1_kernel<<<(n + T - 1) / T, T>>>(cnt, n);
    count_kernel<<<(e + T - 1) / T, T>>>(ei, cnt, e, n);
    dinv_kernel<<<(n + T - 1) / T, T>>>(cnt, dinv, n);
    scan_block_kernel<<<nb, SCAN_B>>>(cnt, incl, bsum, n);
    scan_bsum_kernel<<<1, 256>>>(bsum, nb);
    scan_final_kernel<<<(n + T - 1) / T, T>>>(incl, cnt, bsum, rowptr, fill, n);
    fill_csr_kernel<<<(e + T - 1) / T, T>>>(ei, fill, csr, e, n);

    const int gemm_blocks = (n + 127) / 128;
    const int gather_blocks = (n * 32 + T - 1) / T;

    gemm_tc_kernel<128, false><<<gemm_blocks, 256>>>(x, W1, h16, n);
    gather128_kernel<<<gather_blocks, T>>>(csr, rowptr, cnt, dinv, h16, b1, a, n);

    gemm_tc_kernel<128, true><<<gemm_blocks, 256>>>(a, W2, h16, n);
    gather128_kernel<<<gather_blocks, T>>>(csr, rowptr, cnt, dinv, h16, b2, a, n);

    gemm_tc_kernel<64, true><<<gemm_blocks, 256>>>(a, W3, h16, n);
    gather64_kernel<<<gather_blocks, T>>>(csr, rowptr, cnt, dinv, h16, b3, out, n);
}

// round 11
// speedup vs baseline: 3.7480x; 1.1120x over previous
#include <cuda_runtime.h>
#include <cuda_fp16.h>
#include <cstdint>

// ---------------------------------------------------------------------------
// GCN 3-layer: CSR-gather over dinv-prescaled fp16 rows + 3xTF32 TC GEMM,
// with CSR-build/GEMM1 stream overlap.
// out = GCNConv3(relu(GCNConv2(relu(GCNConv1(x)))))
// GCNConv: out = D^-1/2 (A+I) D^-1/2 (x @ W^T) + b
// Identity: A[d] = b + dinv[d]*( H'[d] + sum_e H'[src] ), H' = dinv*H (fp16)
// ---------------------------------------------------------------------------

#define MAXN 100000
#define MAXE 1600000
#define SCAN_B 1024

__device__ __align__(16) __half g_h16[MAXN * 128];  // dinv-prescaled GEMM out
__device__ __align__(16) float g_a[MAXN * 128];     // gather accumulator (fp32)
__device__ float g_dinv[MAXN];
__device__ int g_cnt[MAXN];
__device__ int g_fill[MAXN];
__device__ int g_rowptr[MAXN];
__device__ int g_incl[MAXN];
__device__ int g_bsum[256];
__device__ int g_csr[MAXE];
__device__ int g_is64;

// streams/events for capture-safe fork-join (no device memory involved)
static cudaStream_t g_s2;
static cudaEvent_t g_ev_fork, g_ev_join;
static bool g_stream_init = []() {
    cudaStreamCreateWithFlags(&g_s2, cudaStreamNonBlocking);
    cudaEventCreateWithFlags(&g_ev_fork, cudaEventDisableTiming);
    cudaEventCreateWithFlags(&g_ev_join, cudaEventDisableTiming);
    return true;
}();

// ---------------------------------------------------------------------------
// tf32 helpers
// ---------------------------------------------------------------------------
__device__ __forceinline__ unsigned to_tf32(float f) {
    unsigned r;
    asm("cvt.rna.tf32.f32 %0, %1;" : "=r"(r) : "f"(f));
    return r;
}
__device__ __forceinline__ void cvt_hl(float v, unsigned& hi, unsigned& lo) {
    hi = to_tf32(v);
    lo = to_tf32(v - __uint_as_float(hi));
}
__device__ __forceinline__ void mma_tf32(float* c, const unsigned* a,
                                         const unsigned* b) {
    asm("mma.sync.aligned.m16n8k8.row.col.f32.tf32.tf32.f32 "
        "{%0,%1,%2,%3},{%4,%5,%6,%7},{%8,%9},{%0,%1,%2,%3};"
        : "+f"(c[0]), "+f"(c[1]), "+f"(c[2]), "+f"(c[3])
        : "r"(a[0]), "r"(a[1]), "r"(a[2]), "r"(a[3]), "r"(b[0]), "r"(b[1]));
}

// ---------------------------------------------------------------------------
// edge dtype probe
// ---------------------------------------------------------------------------
__global__ void probe_init_kernel() { g_is64 = 1; }
__global__ void probe_kernel(const unsigned* __restrict__ ei) {
    int i = blockIdx.x * blockDim.x + threadIdx.x;
    if (i < 1024 && ei[2 * i + 1] != 0) atomicAnd(&g_is64, 0);
}

__device__ __forceinline__ void load_edge(const void* ei, int e, int g, int is64,
                                          int& s, int& d) {
    if (is64) {
        const long long* p = (const long long*)ei;
        s = (int)p[g];
        d = (int)p[e + g];
    } else {
        const int* p = (const int*)ei;
        s = p[g];
        d = p[e + g];
    }
}

// ---------------------------------------------------------------------------
// CSR build
// ---------------------------------------------------------------------------
__global__ void zero1_kernel(int* __restrict__ a, int n) {
    int i = blockIdx.x * blockDim.x + threadIdx.x;
    if (i < n) a[i] = 0;
}

__global__ void count_kernel(const void* __restrict__ ei, int* __restrict__ cnt,
                             int e, int n) {
    int i = blockIdx.x * blockDim.x + threadIdx.x;
    if (i >= e) return;
    int s, d;
    load_edge(ei, e, i, g_is64, s, d);
    if ((unsigned)d < (unsigned)n) atomicAdd(&cnt[d], 1);
}

__global__ void dinv_kernel(const int* __restrict__ cnt, float* __restrict__ dinv,
                            int n) {
    int i = blockIdx.x * blockDim.x + threadIdx.x;
    if (i < n) dinv[i] = rsqrtf((float)cnt[i] + 1.0f);
}

__global__ __launch_bounds__(SCAN_B) void scan_block_kernel(
    const int* __restrict__ cnt, int* __restrict__ incl, int* __restrict__ bsum,
    int n) {
    __shared__ int sm[SCAN_B];
    int i = blockIdx.x * SCAN_B + threadIdx.x;
    int v = (i < n) ? cnt[i] : 0;
    sm[threadIdx.x] = v;
    __syncthreads();
#pragma unroll
    for (int off = 1; off < SCAN_B; off <<= 1) {
        int t = (threadIdx.x >= off) ? sm[threadIdx.x - off] : 0;
        __syncthreads();
        sm[threadIdx.x] += t;
        __syncthreads();
    }
    if (i < n) incl[i] = sm[threadIdx.x];
    if (threadIdx.x == SCAN_B - 1) bsum[blockIdx.x] = sm[SCAN_B - 1];
}

__global__ __launch_bounds__(256) void scan_bsum_kernel(int* __restrict__ bsum,
                                                        int nb) {
    __shared__ int sm[256];
    int v = (threadIdx.x < nb) ? bsum[threadIdx.x] : 0;
    sm[threadIdx.x] = v;
    __syncthreads();
#pragma unroll
    for (int off = 1; off < 256; off <<= 1) {
        int t = (threadIdx.x >= off) ? sm[threadIdx.x - off] : 0;
        __syncthreads();
        sm[threadIdx.x] += t;
        __syncthreads();
    }
    if (threadIdx.x < nb) bsum[threadIdx.x] = sm[threadIdx.x] - v;
}

__global__ void scan_final_kernel(const int* __restrict__ incl,
                                  const int* __restrict__ cnt,
                                  const int* __restrict__ bsum,
                                  int* __restrict__ rowptr,
                                  int* __restrict__ fill, int n) {
    int i = blockIdx.x * blockDim.x + threadIdx.x;
    if (i < n) {
        int rp = incl[i] - cnt[i] + bsum[i / SCAN_B];
        rowptr[i] = rp;
        fill[i] = rp;
    }
}

__global__ void fill_csr_kernel(const void* __restrict__ ei,
                                int* __restrict__ fill, int* __restrict__ csr,
                                int e, int n) {
    int i = blockIdx.x * blockDim.x + threadIdx.x;
    if (i >= e) return;
    int s, d;
    load_edge(ei, e, i, g_is64, s, d);
    if ((unsigned)s >= (unsigned)n || (unsigned)d >= (unsigned)n) return;
    int pos = atomicAdd(&fill[d], 1);
    csr[pos] = s;
}

// ---------------------------------------------------------------------------
// TC GEMM (3xTF32), dinv-prescaled fp16 output:
// H16[r,:] = fp16( dinv[r] * (act(X[r,:]) @ W^T) )
// ---------------------------------------------------------------------------
template <int COLS, bool RELU>
__global__ __launch_bounds__(256) void gemm_tc_kernel(
    const float* __restrict__ X, const float* __restrict__ W,
    const float* __restrict__ dinv, __half* __restrict__ H, int n) {
    __shared__ float xs[128][36];
    __shared__ float ws[COLS][36];

    constexpr int WM = (COLS == 128) ? 2 : 1;
    const int t = threadIdx.x;
    const int wid = t >> 5;
    const int lane = t & 31;
    const int gid = lane >> 2;
    const int tig = lane & 3;
    const int row0 = blockIdx.x * 128;

    int wm0, wn0;
    if (COLS == 128) { wm0 = (wid >> 1) * 32; wn0 = (wid & 1) * 64; }
    else             { wm0 = wid * 16;        wn0 = 0; }

    float acc[WM][8][4];
#pragma unroll
    for (int mt = 0; mt < WM; mt++)
#pragma unroll
        for (int nt = 0; nt < 8; nt++)
#pragma unroll
            for (int i = 0; i < 4; i++) acc[mt][nt][i] = 0.0f;

    for (int kb = 0; kb < 128; kb += 32) {
        for (int idx = t; idx < 128 * 32; idx += 256) {
            int r = idx >> 5, k = idx & 31;
            int row = row0 + r;
            float v = 0.0f;
            if (row < n) {
                v = X[row * 128 + kb + k];
                if (RELU) v = fmaxf(v, 0.0f);
            }
            xs[r][k] = v;
        }
        for (int idx = t; idx < COLS * 32; idx += 256) {
            int c = idx >> 5, k = idx & 31;
            ws[c][k] = W[c * 128 + kb + k];
        }
        __syncthreads();

#pragma unroll
        for (int ks = 0; ks < 4; ks++) {
            const int k0 = ks * 8;
            unsigned a_hi[WM][4], a_lo[WM][4];
#pragma unroll
            for (int mt = 0; mt < WM; mt++) {
                int r = wm0 + mt * 16 + gid;
                cvt_hl(xs[r][k0 + tig],         a_hi[mt][0], a_lo[mt][0]);
                cvt_hl(xs[r + 8][k0 + tig],     a_hi[mt][1], a_lo[mt][1]);
                cvt_hl(xs[r][k0 + tig + 4],     a_hi[mt][2], a_lo[mt][2]);
                cvt_hl(xs[r + 8][k0 + tig + 4], a_hi[mt][3], a_lo[mt][3]);
            }
#pragma unroll
            for (int nt = 0; nt < 8; nt++) {
                int c = wn0 + nt * 8 + gid;
                unsigned b_hi[2], b_lo[2];
                cvt_hl(ws[c][k0 + tig],     b_hi[0], b_lo[0]);
                cvt_hl(ws[c][k0 + tig + 4], b_hi[1], b_lo[1]);
#pragma unroll
                for (int mt = 0; mt < WM; mt++) {
                    mma_tf32(acc[mt][nt], a_hi[mt], b_lo);
                    mma_tf32(acc[mt][nt], a_lo[mt], b_hi);
                    mma_tf32(acc[mt][nt], a_hi[mt], b_hi);
                }
            }
        }
        __syncthreads();
    }

#pragma unroll
    for (int mt = 0; mt < WM; mt++) {
        int r = row0 + wm0 + mt * 16 + gid;
        float d0 = (r < n) ? dinv[r] : 0.0f;
        float d1 = (r + 8 < n) ? dinv[r + 8] : 0.0f;
#pragma unroll
        for (int nt = 0; nt < 8; nt++) {
            int c = wn0 + nt * 8 + tig * 2;
            if (r < n)
                *reinterpret_cast<__half2*>(H + (size_t)r * COLS + c) =
                    __floats2half2_rn(acc[mt][nt][0] * d0, acc[mt][nt][1] * d0);
            if (r + 8 < n)
                *reinterpret_cast<__half2*>(H + (size_t)(r + 8) * COLS + c) =
                    __floats2half2_rn(acc[mt][nt][2] * d1, acc[mt][nt][3] * d1);
        }
    }
}

// ---------------------------------------------------------------------------
// gather (one warp per node), prescaled fp16 rows:
// A[d] = b + dinv[d]*( H'[d] + sum_e H'[src] )
// ---------------------------------------------------------------------------
__global__ __launch_bounds__(256) void gather128_kernel(
    const int* __restrict__ csr, const int* __restrict__ rowptr,
    const int* __restrict__ cnt, const float* __restrict__ dinv,
    const __half* __restrict__ H, const float* __restrict__ b,
    float* __restrict__ A, int n) {
    int warp = (blockIdx.x * blockDim.x + threadIdx.x) >> 5;
    int lane = threadIdx.x & 31;
    if (warp >= n) return;
    const int d = warp;
    const int start = rowptr[d];
    const int c = cnt[d];

    float4 acc;
    {
        uint2 u = reinterpret_cast<const uint2*>(H + (size_t)d * 128)[lane];
        float2 lo = __half22float2(*reinterpret_cast<__half2*>(&u.x));
        float2 hi = __half22float2(*reinterpret_cast<__half2*>(&u.y));
        acc.x = lo.x; acc.y = lo.y; acc.z = hi.x; acc.w = hi.y;
    }

    for (int j0 = 0; j0 < c; j0 += 32) {
        int s = (j0 + lane < c) ? csr[start + j0 + lane] : 0;
        int m = min(32, c - j0);
#pragma unroll 8
        for (int k = 0; k < m; k++) {
            int sk = __shfl_sync(0xffffffffu, s, k);
            uint2 u = reinterpret_cast<const uint2*>(H + (size_t)sk * 128)[lane];
            float2 lo = __half22float2(*reinterpret_cast<__half2*>(&u.x));
            float2 hi = __half22float2(*reinterpret_cast<__half2*>(&u.y));
            acc.x += lo.x; acc.y += lo.y; acc.z += hi.x; acc.w += hi.y;
        }
    }
    const float dd = dinv[d];
    const float4 bv = reinterpret_cast<const float4*>(b)[lane];
    float4 o;
    o.x = fmaf(acc.x, dd, bv.x);
    o.y = fmaf(acc.y, dd, bv.y);
    o.z = fmaf(acc.z, dd, bv.z);
    o.w = fmaf(acc.w, dd, bv.w);
    reinterpret_cast<float4*>(A + (size_t)d * 128)[lane] = o;
}

__global__ __launch_bounds__(256) void gather64_kernel(
    const int* __restrict__ csr, const int* __restrict__ rowptr,
    const int* __restrict__ cnt, const float* __restrict__ dinv,
    const __half* __restrict__ H, const float* __restrict__ b,
    float* __restrict__ A, int n) {
    int warp = (blockIdx.x * blockDim.x + threadIdx.x) >> 5;
    int lane = threadIdx.x & 31;
    if (warp >= n) return;
    const int d = warp;
    const int start = rowptr[d];
    const int c = cnt[d];

    float2 acc;
    {
        unsigned u = reinterpret_cast<const unsigned*>(H + (size_t)d * 64)[lane];
        float2 hv = __half22float2(*reinterpret_cast<__half2*>(&u));
        acc.x = hv.x; acc.y = hv.y;
    }

    for (int j0 = 0; j0 < c; j0 += 32) {
        int s = (j0 + lane < c) ? csr[start + j0 + lane] : 0;
        int m = min(32, c - j0);
#pragma unroll 8
        for (int k = 0; k < m; k++) {
            int sk = __shfl_sync(0xffffffffu, s, k);
            unsigned u = reinterpret_cast<const unsigned*>(H + (size_t)sk * 64)[lane];
            float2 v = __half22float2(*reinterpret_cast<__half2*>(&u));
            acc.x += v.x; acc.y += v.y;
        }
    }
    const float dd = dinv[d];
    const float2 bv = reinterpret_cast<const float2*>(b)[lane];
    float2 o;
    o.x = fmaf(acc.x, dd, bv.x);
    o.y = fmaf(acc.y, dd, bv.y);
    reinterpret_cast<float2*>(A + (size_t)d * 64)[lane] = o;
}

// ---------------------------------------------------------------------------
// launch
// ---------------------------------------------------------------------------
extern "C" void kernel_launch(void* const* d_in, const int* in_sizes, int n_in,
                              void* d_out, int out_size) {
    const float* x = (const float*)d_in[0];
    const void* ei = d_in[1];
    const float* W1 = (const float*)d_in[2];
    const float* b1 = (const float*)d_in[3];
    const float* W2 = (const float*)d_in[4];
    const float* b2 = (const float*)d_in[5];
    const float* W3 = (const float*)d_in[6];
    const float* b3 = (const float*)d_in[7];
    float* out = (float*)d_out;

    const int n = in_sizes[0] / 128;
    const int e = in_sizes[1] / 2;

    __half* h16;
    float *a, *dinv;
    int *cnt, *fill, *rowptr, *incl, *bsum, *csr;
    cudaGetSymbolAddress((void**)&h16, g_h16);
    cudaGetSymbolAddress((void**)&a, g_a);
    cudaGetSymbolAddress((void**)&dinv, g_dinv);
    cudaGetSymbolAddress((void**)&cnt, g_cnt);
    cudaGetSymbolAddress((void**)&fill, g_fill);
    cudaGetSymbolAddress((void**)&rowptr, g_rowptr);
    cudaGetSymbolAddress((void**)&incl, g_incl);
    cudaGetSymbolAddress((void**)&bsum, g_bsum);
    cudaGetSymbolAddress((void**)&csr, g_csr);

    const int T = 256;
    const int nb = (n + SCAN_B - 1) / SCAN_B;
    const int gemm_blocks = (n + 127) / 128;
    const int gather_blocks = (n * 32 + T - 1) / T;

    // prefix on main stream: probe, count, dinv (GEMM1 needs dinv)
    probe_init_kernel<<<1, 1>>>();
    probe_kernel<<<4, 256>>>((const unsigned*)ei);
    zero1_kernel<<<(n + T - 1) / T, T>>>(cnt, n);
    count_kernel<<<(e + T - 1) / T, T>>>(ei, cnt, e, n);
    dinv_kernel<<<(n + T - 1) / T, T>>>(cnt, dinv, n);

    // fork: scan+fill on side stream, GEMM1 on main stream
    cudaEventRecord(g_ev_fork, 0);
    cudaStreamWaitEvent(g_s2, g_ev_fork, 0);

    scan_block_kernel<<<nb, SCAN_B, 0, g_s2>>>(cnt, incl, bsum, n);
    scan_bsum_kernel<<<1, 256, 0, g_s2>>>(bsum, nb);
    scan_final_kernel<<<(n + T - 1) / T, T, 0, g_s2>>>(incl, cnt, bsum, rowptr,
                                                       fill, n);
    fill_csr_kernel<<<(e + T - 1) / T, T, 0, g_s2>>>(ei, fill, csr, e, n);
    cudaEventRecord(g_ev_join, g_s2);

    gemm_tc_kernel<128, false><<<gemm_blocks, 256>>>(x, W1, dinv, h16, n);

    // join before first gather
    cudaStreamWaitEvent(0, g_ev_join, 0);

    gather128_kernel<<<gather_blocks, T>>>(csr, rowptr, cnt, dinv, h16, b1, a, n);

    gemm_tc_kernel<128, true><<<gemm_blocks, 256>>>(a, W2, dinv, h16, n);
    gather128_kernel<<<gather_blocks, T>>>(csr, rowptr, cnt, dinv, h16, b2, a, n);

    gemm_tc_kernel<64, true><<<gemm_blocks, 256>>>(a, W3, dinv, h16, n);
    gather64_kernel<<<gather_blocks, T>>>(csr, rowptr, cnt, dinv, h16, b3, out, n);
}

// round 12
// speedup vs baseline: 4.0631x; 1.0841x over previous
#include <cuda_runtime.h>
#include <cuda_fp16.h>
#include <cstdint>

// ---------------------------------------------------------------------------
// GCN 3-layer: CSR-gather over dinv-prescaled fp16 rows + fp16 2-split
// (m16n8k16 HMMA) GEMM, CSR-build/GEMM1 stream overlap.
// out = GCNConv3(relu(GCNConv2(relu(GCNConv1(x)))))
// GCNConv: out = D^-1/2 (A+I) D^-1/2 (x @ W^T) + b
// Identity: A[d] = b + dinv[d]*( H'[d] + sum_e H'[src] ), H' = dinv*H (fp16)
// GEMM precision: x = hi+lo (fp16 pair), D += hi*lo' + lo*hi' + hi*hi'
//                 (lo*lo' ~ 2^-22 dropped); fp32 accumulate -> ~1e-6 error.
// ---------------------------------------------------------------------------

#define MAXN 100000
#define MAXE 1600000
#define SCAN_B 1024

__device__ __align__(16) __half g_h16[MAXN * 128];  // dinv-prescaled GEMM out
__device__ __align__(16) float g_a[MAXN * 128];     // gather accumulator (fp32)
__device__ float g_dinv[MAXN];
__device__ int g_cnt[MAXN];
__device__ int g_fill[MAXN];
__device__ int g_rowptr[MAXN];
__device__ int g_incl[MAXN];
__device__ int g_bsum[256];
__device__ int g_csr[MAXE];
__device__ int g_is64;

// persistent fp16 hi/lo splits of the (tiny) weight matrices
__device__ __align__(16) __half g_w1h[128 * 128], g_w1l[128 * 128];
__device__ __align__(16) __half g_w2h[128 * 128], g_w2l[128 * 128];
__device__ __align__(16) __half g_w3h[64 * 128],  g_w3l[64 * 128];

// streams/events for capture-safe fork-join (no device memory involved)
static cudaStream_t g_s2;
static cudaEvent_t g_ev_fork, g_ev_join;
static bool g_stream_init = []() {
    cudaStreamCreateWithFlags(&g_s2, cudaStreamNonBlocking);
    cudaEventCreateWithFlags(&g_ev_fork, cudaEventDisableTiming);
    cudaEventCreateWithFlags(&g_ev_join, cudaEventDisableTiming);
    return true;
}();

// ---------------------------------------------------------------------------
// helpers
// ---------------------------------------------------------------------------
__device__ __forceinline__ void split_h(float v, __half& h, __half& l) {
    h = __float2half_rn(v);
    l = __float2half_rn(v - __half2float(h));
}

__device__ __forceinline__ void mma_f16(float* c, const unsigned* a,
                                        const unsigned* b) {
    asm("mma.sync.aligned.m16n8k16.row.col.f32.f16.f16.f32 "
        "{%0,%1,%2,%3},{%4,%5,%6,%7},{%8,%9},{%0,%1,%2,%3};"
        : "+f"(c[0]), "+f"(c[1]), "+f"(c[2]), "+f"(c[3])
        : "r"(a[0]), "r"(a[1]), "r"(a[2]), "r"(a[3]), "r"(b[0]), "r"(b[1]));
}

// ---------------------------------------------------------------------------
// weight pre-split: W (fp32) -> Wh, Wl (fp16)
// ---------------------------------------------------------------------------
__global__ void wconv_kernel(const float* __restrict__ W, __half* __restrict__ wh,
                             __half* __restrict__ wl, int sz) {
    int i = blockIdx.x * blockDim.x + threadIdx.x;
    if (i < sz) {
        __half h, l;
        split_h(W[i], h, l);
        wh[i] = h;
        wl[i] = l;
    }
}

// ---------------------------------------------------------------------------
// edge dtype probe
// ---------------------------------------------------------------------------
__global__ void probe_init_kernel() { g_is64 = 1; }
__global__ void probe_kernel(const unsigned* __restrict__ ei) {
    int i = blockIdx.x * blockDim.x + threadIdx.x;
    if (i < 1024 && ei[2 * i + 1] != 0) atomicAnd(&g_is64, 0);
}

__device__ __forceinline__ void load_edge(const void* ei, int e, int g, int is64,
                                          int& s, int& d) {
    if (is64) {
        const long long* p = (const long long*)ei;
        s = (int)p[g];
        d = (int)p[e + g];
    } else {
        const int* p = (const int*)ei;
        s = p[g];
        d = p[e + g];
    }
}

// ---------------------------------------------------------------------------
// CSR build
// ---------------------------------------------------------------------------
__global__ void zero1_kernel(int* __restrict__ a, int n) {
    int i = blockIdx.x * blockDim.x + threadIdx.x;
    if (i < n) a[i] = 0;
}

__global__ void count_kernel(const void* __restrict__ ei, int* __restrict__ cnt,
                             int e, int n) {
    int i = blockIdx.x * blockDim.x + threadIdx.x;
    if (i >= e) return;
    int s, d;
    load_edge(ei, e, i, g_is64, s, d);
    if ((unsigned)d < (unsigned)n) atomicAdd(&cnt[d], 1);
}

__global__ void dinv_kernel(const int* __restrict__ cnt, float* __restrict__ dinv,
                            int n) {
    int i = blockIdx.x * blockDim.x + threadIdx.x;
    if (i < n) dinv[i] = rsqrtf((float)cnt[i] + 1.0f);
}

__global__ __launch_bounds__(SCAN_B) void scan_block_kernel(
    const int* __restrict__ cnt, int* __restrict__ incl, int* __restrict__ bsum,
    int n) {
    __shared__ int sm[SCAN_B];
    int i = blockIdx.x * SCAN_B + threadIdx.x;
    int v = (i < n) ? cnt[i] : 0;
    sm[threadIdx.x] = v;
    __syncthreads();
#pragma unroll
    for (int off = 1; off < SCAN_B; off <<= 1) {
        int t = (threadIdx.x >= off) ? sm[threadIdx.x - off] : 0;
        __syncthreads();
        sm[threadIdx.x] += t;
        __syncthreads();
    }
    if (i < n) incl[i] = sm[threadIdx.x];
    if (threadIdx.x == SCAN_B - 1) bsum[blockIdx.x] = sm[SCAN_B - 1];
}

__global__ __launch_bounds__(256) void scan_bsum_kernel(int* __restrict__ bsum,
                                                        int nb) {
    __shared__ int sm[256];
    int v = (threadIdx.x < nb) ? bsum[threadIdx.x] : 0;
    sm[threadIdx.x] = v;
    __syncthreads();
#pragma unroll
    for (int off = 1; off < 256; off <<= 1) {
        int t = (threadIdx.x >= off) ? sm[threadIdx.x - off] : 0;
        __syncthreads();
        sm[threadIdx.x] += t;
        __syncthreads();
    }
    if (threadIdx.x < nb) bsum[threadIdx.x] = sm[threadIdx.x] - v;
}

__global__ void scan_final_kernel(const int* __restrict__ incl,
                                  const int* __restrict__ cnt,
                                  const int* __restrict__ bsum,
                                  int* __restrict__ rowptr,
                                  int* __restrict__ fill, int n) {
    int i = blockIdx.x * blockDim.x + threadIdx.x;
    if (i < n) {
        int rp = incl[i] - cnt[i] + bsum[i / SCAN_B];
        rowptr[i] = rp;
        fill[i] = rp;
    }
}

__global__ void fill_csr_kernel(const void* __restrict__ ei,
                                int* __restrict__ fill, int* __restrict__ csr,
                                int e, int n) {
    int i = blockIdx.x * blockDim.x + threadIdx.x;
    if (i >= e) return;
    int s, d;
    load_edge(ei, e, i, g_is64, s, d);
    if ((unsigned)s >= (unsigned)n || (unsigned)d >= (unsigned)n) return;
    int pos = atomicAdd(&fill[d], 1);
    csr[pos] = s;
}

// ---------------------------------------------------------------------------
// fp16 2-split HMMA GEMM: H16[r,:] = fp16( dinv[r] * (act(X[r,:]) @ W^T) )
// 8 warps/block, 128-row tile. COLS=128: warp 32x64; COLS=64: warp 16x64.
// smem: half [rows][40] (stride-40 -> conflict-free fragment LDS).
// ---------------------------------------------------------------------------
template <int COLS, bool RELU>
__global__ __launch_bounds__(256) void gemm_tc_kernel(
    const float* __restrict__ X, const __half* __restrict__ Wh,
    const __half* __restrict__ Wl, const float* __restrict__ dinv,
    __half* __restrict__ H, int n) {
    __shared__ __half xs_h[128][40], xs_l[128][40];
    __shared__ __half ws_h[COLS][40], ws_l[COLS][40];

    constexpr int WM = (COLS == 128) ? 2 : 1;
    const int t = threadIdx.x;
    const int wid = t >> 5;
    const int lane = t & 31;
    const int gid = lane >> 2;
    const int tig = lane & 3;
    const int row0 = blockIdx.x * 128;

    int wm0, wn0;
    if (COLS == 128) { wm0 = (wid >> 1) * 32; wn0 = (wid & 1) * 64; }
    else             { wm0 = wid * 16;        wn0 = 0; }

    float acc[WM][8][4];
#pragma unroll
    for (int mt = 0; mt < WM; mt++)
#pragma unroll
        for (int nt = 0; nt < 8; nt++)
#pragma unroll
            for (int i = 0; i < 4; i++) acc[mt][nt][i] = 0.0f;

    for (int kb = 0; kb < 128; kb += 32) {
        // stage X: fp32 load (+relu) -> hi/lo halves
        for (int idx = t; idx < 128 * 32; idx += 256) {
            int r = idx >> 5, k = idx & 31;
            int row = row0 + r;
            float v = 0.0f;
            if (row < n) {
                v = X[row * 128 + kb + k];
                if (RELU) v = fmaxf(v, 0.0f);
            }
            __half h, l;
            split_h(v, h, l);
            xs_h[r][k] = h;
            xs_l[r][k] = l;
        }
        // stage W: pre-split halves
        for (int idx = t; idx < COLS * 32; idx += 256) {
            int c = idx >> 5, k = idx & 31;
            ws_h[c][k] = Wh[c * 128 + kb + k];
            ws_l[c][k] = Wl[c * 128 + kb + k];
        }
        __syncthreads();

#pragma unroll
        for (int ks = 0; ks < 2; ks++) {
            const int k0 = ks * 16;
            unsigned ah[WM][4], al[WM][4];
#pragma unroll
            for (int mt = 0; mt < WM; mt++) {
                int r = wm0 + mt * 16 + gid;
                ah[mt][0] = *reinterpret_cast<const unsigned*>(&xs_h[r][k0 + tig * 2]);
                ah[mt][1] = *reinterpret_cast<const unsigned*>(&xs_h[r + 8][k0 + tig * 2]);
                ah[mt][2] = *reinterpret_cast<const unsigned*>(&xs_h[r][k0 + tig * 2 + 8]);
                ah[mt][3] = *reinterpret_cast<const unsigned*>(&xs_h[r + 8][k0 + tig * 2 + 8]);
                al[mt][0] = *reinterpret_cast<const unsigned*>(&xs_l[r][k0 + tig * 2]);
                al[mt][1] = *reinterpret_cast<const unsigned*>(&xs_l[r + 8][k0 + tig * 2]);
                al[mt][2] = *reinterpret_cast<const unsigned*>(&xs_l[r][k0 + tig * 2 + 8]);
                al[mt][3] = *reinterpret_cast<const unsigned*>(&xs_l[r + 8][k0 + tig * 2 + 8]);
            }
#pragma unroll
            for (int nt = 0; nt < 8; nt++) {
                int c = wn0 + nt * 8 + gid;
                unsigned bh[2], bl[2];
                bh[0] = *reinterpret_cast<const unsigned*>(&ws_h[c][k0 + tig * 2]);
                bh[1] = *reinterpret_cast<const unsigned*>(&ws_h[c][k0 + tig * 2 + 8]);
                bl[0] = *reinterpret_cast<const unsigned*>(&ws_l[c][k0 + tig * 2]);
                bl[1] = *reinterpret_cast<const unsigned*>(&ws_l[c][k0 + tig * 2 + 8]);
#pragma unroll
                for (int mt = 0; mt < WM; mt++) {
                    mma_f16(acc[mt][nt], ah[mt], bl);
                    mma_f16(acc[mt][nt], al[mt], bh);
                    mma_f16(acc[mt][nt], ah[mt], bh);
                }
            }
        }
        __syncthreads();
    }

#pragma unroll
    for (int mt = 0; mt < WM; mt++) {
        int r = row0 + wm0 + mt * 16 + gid;
        float d0 = (r < n) ? dinv[r] : 0.0f;
        float d1 = (r + 8 < n) ? dinv[r + 8] : 0.0f;
#pragma unroll
        for (int nt = 0; nt < 8; nt++) {
            int c = wn0 + nt * 8 + tig * 2;
            if (r < n)
                *reinterpret_cast<__half2*>(H + (size_t)r * COLS + c) =
                    __floats2half2_rn(acc[mt][nt][0] * d0, acc[mt][nt][1] * d0);
            if (r + 8 < n)
                *reinterpret_cast<__half2*>(H + (size_t)(r + 8) * COLS + c) =
                    __floats2half2_rn(acc[mt][nt][2] * d1, acc[mt][nt][3] * d1);
        }
    }
}

// ---------------------------------------------------------------------------
// gather (one warp per node), prescaled fp16 rows:
// A[d] = b + dinv[d]*( H'[d] + sum_e H'[src] )
// ---------------------------------------------------------------------------
__global__ __launch_bounds__(256) void gather128_kernel(
    const int* __restrict__ csr, const int* __restrict__ rowptr,
    const int* __restrict__ cnt, const float* __restrict__ dinv,
    const __half* __restrict__ H, const float* __restrict__ b,
    float* __restrict__ A, int n) {
    int warp = (blockIdx.x * blockDim.x + threadIdx.x) >> 5;
    int lane = threadIdx.x & 31;
    if (warp >= n) return;
    const int d = warp;
    const int start = rowptr[d];
    const int c = cnt[d];

    float4 acc;
    {
        uint2 u = reinterpret_cast<const uint2*>(H + (size_t)d * 128)[lane];
        float2 lo = __half22float2(*reinterpret_cast<__half2*>(&u.x));
        float2 hi = __half22float2(*reinterpret_cast<__half2*>(&u.y));
        acc.x = lo.x; acc.y = lo.y; acc.z = hi.x; acc.w = hi.y;
    }

    for (int j0 = 0; j0 < c; j0 += 32) {
        int s = (j0 + lane < c) ? csr[start + j0 + lane] : 0;
        int m = min(32, c - j0);
#pragma unroll 8
        for (int k = 0; k < m; k++) {
            int sk = __shfl_sync(0xffffffffu, s, k);
            uint2 u = reinterpret_cast<const uint2*>(H + (size_t)sk * 128)[lane];
            float2 lo = __half22float2(*reinterpret_cast<__half2*>(&u.x));
            float2 hi = __half22float2(*reinterpret_cast<__half2*>(&u.y));
            acc.x += lo.x; acc.y += lo.y; acc.z += hi.x; acc.w += hi.y;
        }
    }
    const float dd = dinv[d];
    const float4 bv = reinterpret_cast<const float4*>(b)[lane];
    float4 o;
    o.x = fmaf(acc.x, dd, bv.x);
    o.y = fmaf(acc.y, dd, bv.y);
    o.z = fmaf(acc.z, dd, bv.z);
    o.w = fmaf(acc.w, dd, bv.w);
    reinterpret_cast<float4*>(A + (size_t)d * 128)[lane] = o;
}

__global__ __launch_bounds__(256) void gather64_kernel(
    const int* __restrict__ csr, const int* __restrict__ rowptr,
    const int* __restrict__ cnt, const float* __restrict__ dinv,
    const __half* __restrict__ H, const float* __restrict__ b,
    float* __restrict__ A, int n) {
    int warp = (blockIdx.x * blockDim.x + threadIdx.x) >> 5;
    int lane = threadIdx.x & 31;
    if (warp >= n) return;
    const int d = warp;
    const int start = rowptr[d];
    const int c = cnt[d];

    float2 acc;
    {
        unsigned u = reinterpret_cast<const unsigned*>(H + (size_t)d * 64)[lane];
        float2 hv = __half22float2(*reinterpret_cast<__half2*>(&u));
        acc.x = hv.x; acc.y = hv.y;
    }

    for (int j0 = 0; j0 < c; j0 += 32) {
        int s = (j0 + lane < c) ? csr[start + j0 + lane] : 0;
        int m = min(32, c - j0);
#pragma unroll 8
        for (int k = 0; k < m; k++) {
            int sk = __shfl_sync(0xffffffffu, s, k);
            unsigned u = reinterpret_cast<const unsigned*>(H + (size_t)sk * 64)[lane];
            float2 v = __half22float2(*reinterpret_cast<__half2*>(&u));
            acc.x += v.x; acc.y += v.y;
        }
    }
    const float dd = dinv[d];
    const float2 bv = reinterpret_cast<const float2*>(b)[lane];
    float2 o;
    o.x = fmaf(acc.x, dd, bv.x);
    o.y = fmaf(acc.y, dd, bv.y);
    reinterpret_cast<float2*>(A + (size_t)d * 64)[lane] = o;
}

// ---------------------------------------------------------------------------
// launch
// ---------------------------------------------------------------------------
extern "C" void kernel_launch(void* const* d_in, const int* in_sizes, int n_in,
                              void* d_out, int out_size) {
    const float* x = (const float*)d_in[0];
    const void* ei = d_in[1];
    const float* W1 = (const float*)d_in[2];
    const float* b1 = (const float*)d_in[3];
    const float* W2 = (const float*)d_in[4];
    const float* b2 = (const float*)d_in[5];
    const float* W3 = (const float*)d_in[6];
    const float* b3 = (const float*)d_in[7];
    float* out = (float*)d_out;

    const int n = in_sizes[0] / 128;
    const int e = in_sizes[1] / 2;

    __half *h16, *w1h, *w1l, *w2h, *w2l, *w3h, *w3l;
    float *a, *dinv;
    int *cnt, *fill, *rowptr, *incl, *bsum, *csr;
    cudaGetSymbolAddress((void**)&h16, g_h16);
    cudaGetSymbolAddress((void**)&a, g_a);
    cudaGetSymbolAddress((void**)&dinv, g_dinv);
    cudaGetSymbolAddress((void**)&cnt, g_cnt);
    cudaGetSymbolAddress((void**)&fill, g_fill);
    cudaGetSymbolAddress((void**)&rowptr, g_rowptr);
    cudaGetSymbolAddress((void**)&incl, g_incl);
    cudaGetSymbolAddress((void**)&bsum, g_bsum);
    cudaGetSymbolAddress((void**)&csr, g_csr);
    cudaGetSymbolAddress((void**)&w1h, g_w1h);
    cudaGetSymbolAddress((void**)&w1l, g_w1l);
    cudaGetSymbolAddress((void**)&w2h, g_w2h);
    cudaGetSymbolAddress((void**)&w2l, g_w2l);
    cudaGetSymbolAddress((void**)&w3h, g_w3h);
    cudaGetSymbolAddress((void**)&w3l, g_w3l);

    const int T = 256;
    const int nb = (n + SCAN_B - 1) / SCAN_B;
    const int gemm_blocks = (n + 127) / 128;
    const int gather_blocks = (n * 32 + T - 1) / T;

    // weight pre-split (tiny) + prefix: probe, count, dinv
    wconv_kernel<<<64, 256>>>(W1, w1h, w1l, 128 * 128);
    wconv_kernel<<<64, 256>>>(W2, w2h, w2l, 128 * 128);
    wconv_kernel<<<32, 256>>>(W3, w3h, w3l, 64 * 128);
    probe_init_kernel<<<1, 1>>>();
    probe_kernel<<<4, 256>>>((const unsigned*)ei);
    zero1_kernel<<<(n + T - 1) / T, T>>>(cnt, n);
    count_kernel<<<(e + T - 1) / T, T>>>(ei, cnt, e, n);
    dinv_kernel<<<(n + T - 1) / T, T>>>(cnt, dinv, n);

    // fork: scan+fill on side stream, GEMM1 on main stream
    cudaEventRecord(g_ev_fork, 0);
    cudaStreamWaitEvent(g_s2, g_ev_fork, 0);

    scan_block_kernel<<<nb, SCAN_B, 0, g_s2>>>(cnt, incl, bsum, n);
    scan_bsum_kernel<<<1, 256, 0, g_s2>>>(bsum, nb);
    scan_final_kernel<<<(n + T - 1) / T, T, 0, g_s2>>>(incl, cnt, bsum, rowptr,
                                                       fill, n);
    fill_csr_kernel<<<(e + T - 1) / T, T, 0, g_s2>>>(ei, fill, csr, e, n);
    cudaEventRecord(g_ev_join, g_s2);

    gemm_tc_kernel<128, false><<<gemm_blocks, 256>>>(x, w1h, w1l, dinv, h16, n);

    // join before first gather
    cudaStreamWaitEvent(0, g_ev_join, 0);

    gather128_kernel<<<gather_blocks, T>>>(csr, rowptr, cnt, dinv, h16, b1, a, n);

    gemm_tc_kernel<128, true><<<gemm_blocks, 256>>>(a, w2h, w2l, dinv, h16, n);
    gather128_kernel<<<gather_blocks, T>>>(csr, rowptr, cnt, dinv, h16, b2, a, n);

    gemm_tc_kernel<64, true><<<gemm_blocks, 256>>>(a, w3h, w3l, dinv, h16, n);
    gather64_kernel<<<gather_blocks, T>>>(csr, rowptr, cnt, dinv, h16, b3, out, n);
}